// round 2
// baseline (speedup 1.0000x reference)
#include <cuda_runtime.h>

// Problem constants (fixed by the reference)
#define N_ROWS 262144
#define D_DIM  768
#define K_DIM  1024

#define BM 128
#define BN 128
#define BK 16
#define TPB 256

// Scratch (no cudaMalloc allowed): transposed centroids + argmin ids
__device__ float g_CT[K_DIM * D_DIM];   // 3 MB
__device__ int   g_idx[N_ROWS];         // 1 MB

// ---------------------------------------------------------------------------
// Kernel 0: transpose C [D,K] -> CT [K,D] so the gather is row-contiguous.
// ---------------------------------------------------------------------------
__global__ void k_transpose(const float* __restrict__ C) {
    __shared__ float tile[32][33];
    const int k0 = blockIdx.x * 32;
    const int d0 = blockIdx.y * 32;
    const int tx = threadIdx.x, ty = threadIdx.y;  // block (32, 8)
    #pragma unroll
    for (int i = 0; i < 4; i++) {
        int d = d0 + ty + i * 8;
        tile[ty + i * 8][tx] = C[d * K_DIM + k0 + tx];
    }
    __syncthreads();
    #pragma unroll
    for (int i = 0; i < 4; i++) {
        int k = k0 + ty + i * 8;
        g_CT[k * D_DIM + d0 + tx] = tile[tx][ty + i * 8];
    }
}

// ---------------------------------------------------------------------------
// Kernel 1: fused GEMM + argmin.
// score(n,k) = Cnorm[k] - 2 * dot(x[n,:], C[:,k]);  g_idx[n] = argmin_k score
// (||x||^2 omitted: constant per row, does not change argmin)
// 128x128 tile, BK=16, 256 threads, 8x8 microtile with packed f32x2 FMAs.
// Rows are blocked (ty*8+i), cols strided (j*16+tx) -> conflict-free smem
// reads AND correct first-min tie-breaking (k increases with j for fixed tx,
// thread-local strict < keeps the smallest k; cross-thread reduce breaks
// ties toward the smaller index).
// ---------------------------------------------------------------------------
__global__ __launch_bounds__(TPB, 2)
void k_argmin(const float* __restrict__ x, const float* __restrict__ C,
              const float* __restrict__ Cnorm) {
    __shared__ float sx[BK][BM + 2];   // pad 130: conflict-free transposed stores
    __shared__ float sc[BK][BN];
    __shared__ float s_cn[K_DIM];
    __shared__ float s_best[BM];
    __shared__ int   s_bidx[BM];

    const int tid = threadIdx.x;
    const int tx = tid & 15;
    const int ty = tid >> 4;
    const int row0 = blockIdx.x * BM;

    for (int i = tid; i < K_DIM; i += TPB) s_cn[i] = Cnorm[i];
    if (tid < BM) { s_best[tid] = __int_as_float(0x7f800000); s_bidx[tid] = 0; }
    __syncthreads();

    for (int kc = 0; kc < K_DIM; kc += BN) {
        unsigned long long acc[4][8];   // 4 packed row-pairs x 8 cols
        #pragma unroll
        for (int i = 0; i < 4; i++)
            #pragma unroll
            for (int j = 0; j < 8; j++) acc[i][j] = 0ull;

        for (int d0 = 0; d0 < D_DIM; d0 += BK) {
            // x tile: sx[d][r]  (lane-consecutive d -> 64B global segments;
            // store bank = (2d+r)%32, d distinct across lanes -> conflict-free)
            {
                const int d = tid & 15;
                const float* xp = x + (long long)row0 * D_DIM + d0 + d;
                #pragma unroll
                for (int it = 0; it < BM / 16; it++) {
                    int r = (tid >> 4) + it * 16;
                    sx[d][r] = xp[(long long)r * D_DIM];
                }
            }
            // C tile: sc[dd][c]  (fully coalesced, conflict-free)
            {
                const int c = tid & 127;
                const int dbase = tid >> 7;
                const float* cp = C + (long long)d0 * K_DIM + kc + c;
                #pragma unroll
                for (int it = 0; it < BK / 2; it++) {
                    int dd = dbase + it * 2;
                    sc[dd][c] = cp[(long long)dd * K_DIM];
                }
            }
            __syncthreads();

            #pragma unroll
            for (int d = 0; d < BK; d++) {
                unsigned long long a2[4], b2[8];
                const float2* arow = reinterpret_cast<const float2*>(&sx[d][ty * 8]);
                #pragma unroll
                for (int i = 0; i < 4; i++) {
                    float2 v = arow[i];                       // rows 2i, 2i+1 (broadcast)
                    a2[i] = *reinterpret_cast<unsigned long long*>(&v);
                }
                #pragma unroll
                for (int j = 0; j < 8; j++) {
                    float b = sc[d][j * 16 + tx];             // conflict-free
                    float2 v = make_float2(b, b);
                    b2[j] = *reinterpret_cast<unsigned long long*>(&v);
                }
                #pragma unroll
                for (int i = 0; i < 4; i++)
                    #pragma unroll
                    for (int j = 0; j < 8; j++)
                        asm("fma.rn.f32x2 %0, %1, %2, %0;"
                            : "+l"(acc[i][j]) : "l"(a2[i]), "l"(b2[j]));
            }
            __syncthreads();
        }

        // Per-row argmin over this 128-column chunk, then fold into running min.
        #pragma unroll
        for (int i = 0; i < 8; i++) {
            const int i2 = i >> 1, hi = i & 1;
            float best = __int_as_float(0x7f800000);
            int bidx = 0;
            #pragma unroll
            for (int j = 0; j < 8; j++) {
                float2 v = *reinterpret_cast<float2*>(&acc[i2][j]);
                float dot = hi ? v.y : v.x;
                int k = kc + j * 16 + tx;
                float val = s_cn[k] - 2.0f * dot;
                if (val < best) { best = val; bidx = k; }   // strict <: first min wins
            }
            #pragma unroll
            for (int off = 8; off > 0; off >>= 1) {
                float ov = __shfl_down_sync(0xffffffffu, best, off, 16);
                int   oi = __shfl_down_sync(0xffffffffu, bidx, off, 16);
                if (ov < best || (ov == best && oi < bidx)) { best = ov; bidx = oi; }
            }
            if (tx == 0) {
                const int r = ty * 8 + i;   // unique writer per row
                if (best < s_best[r] || (best == s_best[r] && bidx < s_bidx[r])) {
                    s_best[r] = best; s_bidx[r] = bidx;
                }
            }
        }
    }
    __syncthreads();
    if (tid < BM) g_idx[row0 + tid] = s_bidx[tid];
}

// ---------------------------------------------------------------------------
// Kernel 2: gather — out[n,:] = CT[idx[n],:]  (CT is L2-resident, 3 MB)
// One block per row, 192 threads x float4 = 768 floats.
// ---------------------------------------------------------------------------
__global__ void k_gather(float* __restrict__ out) {
    const int n = blockIdx.x;
    const int k = g_idx[n];
    const float4* src = reinterpret_cast<const float4*>(g_CT + (long long)k * D_DIM);
    float4* dst = reinterpret_cast<float4*>(out + (long long)n * D_DIM);
    dst[threadIdx.x] = src[threadIdx.x];
}

extern "C" void kernel_launch(void* const* d_in, const int* in_sizes, int n_in,
                              void* d_out, int out_size) {
    const float* x     = (const float*)d_in[0];
    const float* C     = (const float*)d_in[1];
    const float* Cnorm = (const float*)d_in[2];
    float* out = (float*)d_out;

    dim3 tb(32, 8);
    dim3 tg(K_DIM / 32, D_DIM / 32);
    k_transpose<<<tg, tb>>>(C);

    k_argmin<<<N_ROWS / BM, TPB>>>(x, C, Cnorm);

    k_gather<<<N_ROWS, 192>>>(out);
}

// round 5
// speedup vs baseline: 1.6418x; 1.6418x over previous
#include <cuda_runtime.h>
#include <cuda_bf16.h>
#include <cstdint>

#define N_ROWS 262144
#define D_DIM  768
#define K_DIM  1024

// ---------------- device scratch ----------------
__device__ float         g_ct [K_DIM * D_DIM];   // fp32 C^T for gather
__device__ __nv_bfloat16 g_bhi[K_DIM * D_DIM];   // bf16 hi of C^T (K-major)
__device__ __nv_bfloat16 g_blo[K_DIM * D_DIM];   // bf16 lo of C^T
__device__ int           g_idx[N_ROWS];
__device__ int           g_fix_count;
__device__ int           g_fix_rows[32768];

// ---------------- helpers ----------------
__device__ __forceinline__ uint32_t smem_u32(const void* p) {
    uint32_t a;
    asm("{ .reg .u64 t; cvta.to.shared.u64 t, %1; cvt.u32.u64 %0, t; }" : "=r"(a) : "l"(p));
    return a;
}
__device__ __forceinline__ void cpa16(uint32_t dst, const void* src) {
    asm volatile("{ .reg .u64 p; cvta.to.global.u64 p, %1; cp.async.cg.shared.global [%0], [p], 16; }"
                 :: "r"(dst), "l"(src));
}
__device__ __forceinline__ void ldsm4(uint32_t* r, uint32_t a) {
    asm volatile("ldmatrix.sync.aligned.m8n8.x4.shared.b16 {%0,%1,%2,%3}, [%4];"
                 : "=r"(r[0]), "=r"(r[1]), "=r"(r[2]), "=r"(r[3]) : "r"(a));
}
__device__ __forceinline__ void mma16816(float* c, const uint32_t* a, uint32_t b0, uint32_t b1) {
    asm volatile("mma.sync.aligned.m16n8k16.row.col.f32.bf16.bf16.f32 "
                 "{%0,%1,%2,%3},{%4,%5,%6,%7},{%8,%9},{%0,%1,%2,%3};"
                 : "+f"(c[0]), "+f"(c[1]), "+f"(c[2]), "+f"(c[3])
                 : "r"(a[0]), "r"(a[1]), "r"(a[2]), "r"(a[3]), "r"(b0), "r"(b1));
}
__device__ __forceinline__ uint32_t pack2(float a, float b) {
    __nv_bfloat162 t = __floats2bfloat162_rn(a, b);
    return *reinterpret_cast<uint32_t*>(&t);
}

// ---------------- smem layout (dynamic) ----------------
#define SM_CN   0        // 1024 f32
#define SM_PB   4096     // 4 x 128 f32
#define SM_PS   6144
#define SM_PI   8192
#define SM_BEST 10240    // 128 f32
#define SM_SEC  10752
#define SM_BIDX 11264
#define SM_STG  12288
#define STG_BYTES 61440  // per stage
#define A_HI 0           // 128 x 80B
#define A_LO 10240
#define B_HI 20480       // 256 x 80B
#define B_LO 40960
#define SMEM_TOTAL (12288 + 2 * 61440)   // 135168

// ---------------------------------------------------------------------------
// Kernel 0: C -> fp32 C^T + bf16 hi/lo C^T; zero fixup counter
// ---------------------------------------------------------------------------
__global__ void k_prep(const float* __restrict__ C) {
    int idx = blockIdx.x * 256 + threadIdx.x;    // idx = d*1024 + k
    if (idx == 0) g_fix_count = 0;
    int d = idx >> 10, k = idx & 1023;
    float v = C[idx];
    __nv_bfloat16 hi = __float2bfloat16_rn(v);
    __nv_bfloat16 lo = __float2bfloat16_rn(v - __bfloat162float(hi));
    size_t o = (size_t)k * D_DIM + d;
    g_ct[o] = v; g_bhi[o] = hi; g_blo[o] = lo;
}

// ---------------------------------------------------------------------------
// Kernel 1: bf16x3 mma.sync GEMM + argmin with margin tracking
// CTA: 128 rows x (4 chunks of 256 cols). 512 threads, warp grid 4x4,
// warp tile 32x64 (2 m16-tiles x 8 n8-tiles).
// ---------------------------------------------------------------------------
__global__ void __launch_bounds__(512, 1)
k_main(const float* __restrict__ x, const float* __restrict__ cnorm) {
    extern __shared__ char sm[];
    const uint32_t sbase = smem_u32(sm);
    const int tid  = threadIdx.x;
    const int lane = tid & 31, warp = tid >> 5;
    const int wm = warp >> 2, wn = warp & 3;
    const int row0 = blockIdx.x * 128;

    float* scn    = (float*)(sm + SM_CN);
    float* s_pb   = (float*)(sm + SM_PB);
    float* s_ps   = (float*)(sm + SM_PS);
    int*   s_pi   = (int*)  (sm + SM_PI);
    float* s_best = (float*)(sm + SM_BEST);
    float* s_sec  = (float*)(sm + SM_SEC);
    int*   s_bidx = (int*)  (sm + SM_BIDX);

    for (int i = tid; i < K_DIM; i += 512) scn[i] = cnorm[i];
    if (tid < 128) {
        s_best[tid] = __int_as_float(0x7f800000);
        s_sec[tid]  = __int_as_float(0x7f800000);
        s_bidx[tid] = 0;
    }
    __syncthreads();

    // A fill mapping: thread -> (row ar, 8 floats at col aq*8)
    const int ar = tid >> 2, aq = tid & 3;
    const float* xp = x + (size_t)(row0 + ar) * D_DIM + aq * 8;
    const uint32_t a_sts_off = (uint32_t)(ar * 80 + aq * 16);

    // ldmatrix lane base offsets
    const uint32_t a_ld = (uint32_t)((wm * 32 + (lane & 15)) * 80 + (lane >> 4) * 16);
    const uint32_t b_ld = (uint32_t)((wn * 64 + (lane & 7) + ((lane & 16) ? 8 : 0)) * 80
                                     + ((lane >> 3) & 1) * 16);

    for (int cc = 0; cc < 4; cc++) {
        const int col0 = cc * 256;
        float acc[2][8][4];
        #pragma unroll
        for (int mt = 0; mt < 2; mt++)
            #pragma unroll
            for (int nt = 0; nt < 8; nt++)
                #pragma unroll
                for (int c = 0; c < 4; c++) acc[mt][nt][c] = 0.f;

        // ---- prologue: fill stage 0 with chunk 0 ----
        {
            #pragma unroll
            for (int i = 0; i < 4; i++) {
                int idx = tid + i * 512;
                int arr = idx >> 10, rem = idx & 1023;
                int n = rem >> 2, q = rem & 3;
                const __nv_bfloat16* src = (arr ? g_blo : g_bhi)
                    + (size_t)(col0 + n) * D_DIM + q * 8;
                uint32_t dst = sbase + SM_STG + (arr ? B_LO : B_HI) + n * 80 + q * 16;
                cpa16(dst, src);
            }
            asm volatile("cp.async.commit_group;");
            float4 v0 = *(const float4*)(xp);
            float4 v1 = *(const float4*)(xp + 4);
            float f[8] = {v0.x, v0.y, v0.z, v0.w, v1.x, v1.y, v1.z, v1.w};
            uint32_t h[4], l[4];
            #pragma unroll
            for (int j = 0; j < 4; j++) {
                __nv_bfloat16 h0 = __float2bfloat16_rn(f[2*j]);
                __nv_bfloat16 h1 = __float2bfloat16_rn(f[2*j+1]);
                h[j] = pack2(f[2*j], f[2*j+1]);
                l[j] = pack2(f[2*j]   - __bfloat162float(h0),
                             f[2*j+1] - __bfloat162float(h1));
            }
            uint32_t da = sbase + SM_STG + A_HI + a_sts_off;
            asm volatile("st.shared.v4.b32 [%0], {%1,%2,%3,%4};" :: "r"(da), "r"(h[0]),"r"(h[1]),"r"(h[2]),"r"(h[3]));
            asm volatile("st.shared.v4.b32 [%0], {%1,%2,%3,%4};" :: "r"(da + (A_LO - A_HI)), "r"(l[0]),"r"(l[1]),"r"(l[2]),"r"(l[3]));
        }

        for (int dc = 0; dc < 24; dc++) {
            const int buf = dc & 1;
            asm volatile("cp.async.wait_group 0;");
            __syncthreads();

            float4 nv0, nv1;
            const bool more = (dc < 23);
            if (more) {
                const int d0n = (dc + 1) * 32;
                #pragma unroll
                for (int i = 0; i < 4; i++) {
                    int idx = tid + i * 512;
                    int arr = idx >> 10, rem = idx & 1023;
                    int n = rem >> 2, q = rem & 3;
                    const __nv_bfloat16* src = (arr ? g_blo : g_bhi)
                        + (size_t)(col0 + n) * D_DIM + d0n + q * 8;
                    uint32_t dst = sbase + SM_STG + (buf ^ 1) * STG_BYTES
                                 + (arr ? B_LO : B_HI) + n * 80 + q * 16;
                    cpa16(dst, src);
                }
                asm volatile("cp.async.commit_group;");
                nv0 = *(const float4*)(xp + d0n);
                nv1 = *(const float4*)(xp + d0n + 4);
            }

            // ---- compute: 3 products x 2 k16-steps x 16 mmas ----
            const uint32_t stg = sbase + SM_STG + buf * STG_BYTES;
            #pragma unroll
            for (int pr = 0; pr < 3; pr++) {
                const uint32_t ab = stg + (pr == 2 ? A_LO : A_HI) + a_ld;
                const uint32_t bb = stg + (pr == 1 ? B_LO : B_HI) + b_ld;
                #pragma unroll
                for (int ks = 0; ks < 2; ks++) {
                    uint32_t afr[2][4];
                    ldsm4(afr[0], ab + ks * 32);
                    ldsm4(afr[1], ab + 1280 + ks * 32);      // mt=1: +16 rows*80B
                    uint32_t bfr[4][4];
                    #pragma unroll
                    for (int bt = 0; bt < 4; bt++)
                        ldsm4(bfr[bt], bb + bt * 1280 + ks * 32);
                    #pragma unroll
                    for (int mt = 0; mt < 2; mt++)
                        #pragma unroll
                        for (int nt = 0; nt < 8; nt++)
                            mma16816(acc[mt][nt], afr[mt],
                                     bfr[nt >> 1][(nt & 1) * 2],
                                     bfr[nt >> 1][(nt & 1) * 2 + 1]);
                }
            }

            if (more) {   // convert + store A for next chunk (LDG landed during mmas)
                float f[8] = {nv0.x, nv0.y, nv0.z, nv0.w, nv1.x, nv1.y, nv1.z, nv1.w};
                uint32_t h[4], l[4];
                #pragma unroll
                for (int j = 0; j < 4; j++) {
                    __nv_bfloat16 h0 = __float2bfloat16_rn(f[2*j]);
                    __nv_bfloat16 h1 = __float2bfloat16_rn(f[2*j+1]);
                    h[j] = pack2(f[2*j], f[2*j+1]);
                    l[j] = pack2(f[2*j]   - __bfloat162float(h0),
                                 f[2*j+1] - __bfloat162float(h1));
                }
                uint32_t da = sbase + SM_STG + (buf ^ 1) * STG_BYTES + A_HI + a_sts_off;
                asm volatile("st.shared.v4.b32 [%0], {%1,%2,%3,%4};" :: "r"(da), "r"(h[0]),"r"(h[1]),"r"(h[2]),"r"(h[3]));
                asm volatile("st.shared.v4.b32 [%0], {%1,%2,%3,%4};" :: "r"(da + (A_LO - A_HI)), "r"(l[0]),"r"(l[1]),"r"(l[2]),"r"(l[3]));
            }
        }

        // ---- epilogue for this 256-col chunk ----
        #pragma unroll
        for (int mt = 0; mt < 2; mt++) {
            #pragma unroll
            for (int h = 0; h < 2; h++) {
                float bv = __int_as_float(0x7f800000);
                float sv = __int_as_float(0x7f800000);
                int bi = 0;
                #pragma unroll
                for (int nt = 0; nt < 8; nt++) {
                    int k0 = col0 + wn * 64 + nt * 8 + (lane & 3) * 2;
                    float v0 = scn[k0]     - 2.0f * acc[mt][nt][h * 2];
                    float v1 = scn[k0 + 1] - 2.0f * acc[mt][nt][h * 2 + 1];
                    if (v0 < bv)      { sv = bv; bv = v0; bi = k0; }
                    else if (v0 < sv) { sv = v0; }
                    if (v1 < bv)      { sv = bv; bv = v1; bi = k0 + 1; }
                    else if (v1 < sv) { sv = v1; }
                }
                #pragma unroll
                for (int m = 1; m <= 2; m <<= 1) {
                    float b2 = __shfl_xor_sync(0xffffffffu, bv, m);
                    float s2 = __shfl_xor_sync(0xffffffffu, sv, m);
                    int   i2 = __shfl_xor_sync(0xffffffffu, bi, m);
                    if (b2 < bv || (b2 == bv && i2 < bi)) {
                        sv = fminf(bv, fminf(sv, s2)); bv = b2; bi = i2;
                    } else {
                        sv = fminf(fminf(sv, s2), b2);
                    }
                }
                if ((lane & 3) == 0) {
                    int row = wm * 32 + mt * 16 + h * 8 + (lane >> 2);
                    s_pb[wn * 128 + row] = bv;
                    s_ps[wn * 128 + row] = sv;
                    s_pi[wn * 128 + row] = bi;
                }
            }
        }
        __syncthreads();
        if (tid < 128) {
            float B = s_pb[tid], S = s_ps[tid]; int I = s_pi[tid];
            #pragma unroll
            for (int w = 1; w < 4; w++) {
                float b2 = s_pb[w * 128 + tid], s2 = s_ps[w * 128 + tid];
                int i2 = s_pi[w * 128 + tid];
                if (b2 < B) { S = fminf(B, fminf(S, s2)); B = b2; I = i2; }
                else        { S = fminf(fminf(S, s2), b2); }
            }
            float rB = s_best[tid], rS = s_sec[tid]; int rI = s_bidx[tid];
            if (B < rB) { rS = fminf(rB, fminf(rS, S)); rB = B; rI = I; }
            else        { rS = fminf(fminf(rS, S), B); }
            s_best[tid] = rB; s_sec[tid] = rS; s_bidx[tid] = rI;
        }
        __syncthreads();
    }

    if (tid < 128) {
        int n = row0 + tid;
        g_idx[n] = s_bidx[tid];
        if (s_sec[tid] - s_best[tid] < 0.02f) {
            int slot = atomicAdd(&g_fix_count, 1);
            if (slot < 32768) g_fix_rows[slot] = n;
        }
    }
}

// ---------------------------------------------------------------------------
// Kernel 2: exact fp32 recheck of low-margin rows
// ---------------------------------------------------------------------------
__global__ void k_fixup(const float* __restrict__ x, const float* __restrict__ C,
                        const float* __restrict__ cnorm) {
    __shared__ float s_x[D_DIM];
    __shared__ float rv[256];
    __shared__ int   rk[256];
    const int tid = threadIdx.x;
    int cnt = g_fix_count; if (cnt > 32768) cnt = 32768;

    for (int j = blockIdx.x; j < cnt; j += gridDim.x) {
        const int n = g_fix_rows[j];
        for (int d = tid; d < D_DIM; d += 256) s_x[d] = x[(size_t)n * D_DIM + d];
        __syncthreads();
        float best = __int_as_float(0x7f800000); int bk = 0;
        for (int k0 = 0; k0 < K_DIM; k0 += 256) {
            int k = k0 + tid;
            float s = 0.f;
            #pragma unroll 4
            for (int d = 0; d < D_DIM; d++) s = fmaf(s_x[d], C[(size_t)d * K_DIM + k], s);
            float val = cnorm[k] - 2.0f * s;
            if (val < best) { best = val; bk = k; }
        }
        rv[tid] = best; rk[tid] = bk;
        __syncthreads();
        for (int off = 128; off > 0; off >>= 1) {
            if (tid < off) {
                if (rv[tid + off] < rv[tid] ||
                    (rv[tid + off] == rv[tid] && rk[tid + off] < rk[tid])) {
                    rv[tid] = rv[tid + off]; rk[tid] = rk[tid + off];
                }
            }
            __syncthreads();
        }
        if (tid == 0) g_idx[n] = rk[0];
        __syncthreads();
    }
}

// ---------------------------------------------------------------------------
// Kernel 3: gather — out[n,:] = CT[idx[n],:]
// ---------------------------------------------------------------------------
__global__ void k_gather(float* __restrict__ out) {
    const int n = blockIdx.x;
    const int k = g_idx[n];
    const float4* src = reinterpret_cast<const float4*>(g_ct + (size_t)k * D_DIM);
    float4* dst = reinterpret_cast<float4*>(out + (size_t)n * D_DIM);
    dst[threadIdx.x] = src[threadIdx.x];
}

extern "C" void kernel_launch(void* const* d_in, const int* in_sizes, int n_in,
                              void* d_out, int out_size) {
    const float* x     = (const float*)d_in[0];
    const float* C     = (const float*)d_in[1];
    const float* Cnorm = (const float*)d_in[2];
    float* out = (float*)d_out;

    static bool attr_set = false;
    if (!attr_set) {
        cudaFuncSetAttribute(k_main, cudaFuncAttributeMaxDynamicSharedMemorySize, SMEM_TOTAL);
        attr_set = true;
    }

    k_prep<<<(K_DIM * D_DIM) / 256, 256>>>(C);
    k_main<<<N_ROWS / 128, 512, SMEM_TOTAL>>>(x, Cnorm);
    k_fixup<<<256, 256>>>(x, C, Cnorm);
    k_gather<<<N_ROWS, 192>>>(out);
}

// round 7
// speedup vs baseline: 1.7901x; 1.0903x over previous
#include <cuda_runtime.h>
#include <cuda_fp16.h>
#include <cstdint>

#define N_ROWS 262144
#define D_DIM  768
#define K_DIM  1024

// ---------------- device scratch ----------------
__device__ float  g_ct [K_DIM * D_DIM];   // fp32 C^T (gather + exact fixup)
__device__ __half g_bhi[K_DIM * D_DIM];   // fp16 C^T (K-major)
__device__ int    g_idx[N_ROWS];
__device__ int    g_fix_count;
__device__ int    g_fix_rows[32768];

// ---------------- helpers ----------------
__device__ __forceinline__ uint32_t smem_u32(const void* p) {
    uint32_t a;
    asm("{ .reg .u64 t; cvta.to.shared.u64 t, %1; cvt.u32.u64 %0, t; }" : "=r"(a) : "l"(p));
    return a;
}
__device__ __forceinline__ void cpa16(uint32_t dst, const void* src) {
    asm volatile("{ .reg .u64 p; cvta.to.global.u64 p, %1; cp.async.cg.shared.global [%0], [p], 16; }"
                 :: "r"(dst), "l"(src));
}
__device__ __forceinline__ void ldsm4(uint32_t* r, uint32_t a) {
    asm volatile("ldmatrix.sync.aligned.m8n8.x4.shared.b16 {%0,%1,%2,%3}, [%4];"
                 : "=r"(r[0]), "=r"(r[1]), "=r"(r[2]), "=r"(r[3]) : "r"(a));
}
__device__ __forceinline__ void mma16816(float* c, const uint32_t* a, uint32_t b0, uint32_t b1) {
    asm volatile("mma.sync.aligned.m16n8k16.row.col.f32.f16.f16.f32 "
                 "{%0,%1,%2,%3},{%4,%5,%6,%7},{%8,%9},{%0,%1,%2,%3};"
                 : "+f"(c[0]), "+f"(c[1]), "+f"(c[2]), "+f"(c[3])
                 : "r"(a[0]), "r"(a[1]), "r"(a[2]), "r"(a[3]), "r"(b0), "r"(b1));
}
__device__ __forceinline__ uint32_t packh2(float a, float b) {
    __half2 t = __floats2half2_rn(a, b);
    return *reinterpret_cast<uint32_t*>(&t);
}

#define FIX_THRESH 0.30f

// ---------------- smem layout (dynamic) ----------------
#define SM_CN   0        // 1024 f32
#define SM_PB   4096     // 4 x 128 f32 partials
#define SM_PS   6144
#define SM_PI   8192
#define SM_BEST 10240
#define SM_SEC  10752
#define SM_BIDX 11264
#define SM_STG  12288
#define STG_BYTES 30720  // per stage: A 128x80B + B 256x80B
#define A_HI 0
#define B_HI 10240
#define SMEM_TOTAL (12288 + 2 * 30720)   // 73728

// ---------------------------------------------------------------------------
// Kernel 0: C -> fp32 C^T + fp16 C^T; zero fixup counter
// ---------------------------------------------------------------------------
__global__ void k_prep(const float* __restrict__ C) {
    int idx = blockIdx.x * 256 + threadIdx.x;    // idx = d*1024 + k
    if (idx == 0) g_fix_count = 0;
    int d = idx >> 10, k = idx & 1023;
    float v = C[idx];
    size_t o = (size_t)k * D_DIM + d;
    g_ct[o] = v; g_bhi[o] = __float2half_rn(v);
}

// ---------------------------------------------------------------------------
// Kernel 1: single-product fp16 mma.sync GEMM + argmin with margin tracking
// CTA: 128 rows x (4 chunks of 256 cols). 512 threads, warp grid 4x4,
// warp tile 32x64 (2 m16 x 8 n8).
// ---------------------------------------------------------------------------
__global__ void __launch_bounds__(512, 1)
k_main(const float* __restrict__ x, const float* __restrict__ cnorm) {
    extern __shared__ char sm[];
    const uint32_t sbase = smem_u32(sm);
    const int tid  = threadIdx.x;
    const int lane = tid & 31, warp = tid >> 5;
    const int wm = warp >> 2, wn = warp & 3;
    const int row0 = blockIdx.x * 128;

    float* scn    = (float*)(sm + SM_CN);
    float* s_pb   = (float*)(sm + SM_PB);
    float* s_ps   = (float*)(sm + SM_PS);
    int*   s_pi   = (int*)  (sm + SM_PI);
    float* s_best = (float*)(sm + SM_BEST);
    float* s_sec  = (float*)(sm + SM_SEC);
    int*   s_bidx = (int*)  (sm + SM_BIDX);

    for (int i = tid; i < K_DIM; i += 512) scn[i] = cnorm[i];
    if (tid < 128) {
        s_best[tid] = __int_as_float(0x7f800000);
        s_sec[tid]  = __int_as_float(0x7f800000);
        s_bidx[tid] = 0;
    }
    __syncthreads();

    // A fill mapping: thread -> (row ar, 8 floats at col aq*8)
    const int ar = tid >> 2, aq = tid & 3;
    const float* xp = x + (size_t)(row0 + ar) * D_DIM + aq * 8;
    const uint32_t a_sts = (uint32_t)(ar * 80 + aq * 16);

    // ldmatrix lane base offsets (proven in R5)
    const uint32_t a_ld = (uint32_t)((wm * 32 + (lane & 15)) * 80 + (lane >> 4) * 16);
    const uint32_t b_ld = (uint32_t)((wn * 64 + (lane & 7) + ((lane & 16) ? 8 : 0)) * 80
                                     + ((lane >> 3) & 1) * 16);

    for (int cc = 0; cc < 4; cc++) {
        const int col0 = cc * 256;
        float acc[2][8][4];
        #pragma unroll
        for (int mt = 0; mt < 2; mt++)
            #pragma unroll
            for (int nt = 0; nt < 8; nt++)
                #pragma unroll
                for (int c = 0; c < 4; c++) acc[mt][nt][c] = 0.f;

        // ---- prologue: fill stage 0 ----
        {
            #pragma unroll
            for (int i = 0; i < 2; i++) {
                int idx = tid + i * 512;
                int n = idx >> 2, q = idx & 3;
                cpa16(sbase + SM_STG + B_HI + n * 80 + q * 16,
                      g_bhi + (size_t)(col0 + n) * D_DIM + q * 8);
            }
            asm volatile("cp.async.commit_group;");
            float4 v0 = *(const float4*)(xp);
            float4 v1 = *(const float4*)(xp + 4);
            uint32_t h[4] = { packh2(v0.x, v0.y), packh2(v0.z, v0.w),
                              packh2(v1.x, v1.y), packh2(v1.z, v1.w) };
            asm volatile("st.shared.v4.b32 [%0], {%1,%2,%3,%4};"
                         :: "r"(sbase + SM_STG + A_HI + a_sts),
                            "r"(h[0]), "r"(h[1]), "r"(h[2]), "r"(h[3]));
        }

        for (int dc = 0; dc < 24; dc++) {
            const int buf = dc & 1;
            asm volatile("cp.async.wait_group 0;");
            __syncthreads();

            float4 nv0, nv1;
            const bool more = (dc < 23);
            if (more) {
                const int d0n = (dc + 1) * 32;
                #pragma unroll
                for (int i = 0; i < 2; i++) {
                    int idx = tid + i * 512;
                    int n = idx >> 2, q = idx & 3;
                    cpa16(sbase + SM_STG + (buf ^ 1) * STG_BYTES + B_HI + n * 80 + q * 16,
                          g_bhi + (size_t)(col0 + n) * D_DIM + d0n + q * 8);
                }
                asm volatile("cp.async.commit_group;");
                nv0 = *(const float4*)(xp + d0n);
                nv1 = *(const float4*)(xp + d0n + 4);
            }

            // ---- compute: 2 k16-steps x 16 mmas ----
            const uint32_t stg = sbase + SM_STG + buf * STG_BYTES;
            const uint32_t ab = stg + A_HI + a_ld;
            const uint32_t bb = stg + B_HI + b_ld;
            #pragma unroll
            for (int ks = 0; ks < 2; ks++) {
                uint32_t afr[2][4];
                ldsm4(afr[0], ab + ks * 32);
                ldsm4(afr[1], ab + 1280 + ks * 32);          // +16 rows * 80B
                uint32_t bfr[4][4];
                #pragma unroll
                for (int bt = 0; bt < 4; bt++)
                    ldsm4(bfr[bt], bb + bt * 1280 + ks * 32);
                #pragma unroll
                for (int mt = 0; mt < 2; mt++)
                    #pragma unroll
                    for (int nt = 0; nt < 8; nt++)
                        mma16816(acc[mt][nt], afr[mt],
                                 bfr[nt >> 1][(nt & 1) * 2],
                                 bfr[nt >> 1][(nt & 1) * 2 + 1]);
            }

            if (more) {
                uint32_t h[4] = { packh2(nv0.x, nv0.y), packh2(nv0.z, nv0.w),
                                  packh2(nv1.x, nv1.y), packh2(nv1.z, nv1.w) };
                asm volatile("st.shared.v4.b32 [%0], {%1,%2,%3,%4};"
                             :: "r"(sbase + SM_STG + (buf ^ 1) * STG_BYTES + A_HI + a_sts),
                                "r"(h[0]), "r"(h[1]), "r"(h[2]), "r"(h[3]));
            }
        }

        // ---- epilogue for this 256-col chunk (best + second-best + index) ----
        #pragma unroll
        for (int mt = 0; mt < 2; mt++) {
            #pragma unroll
            for (int h = 0; h < 2; h++) {
                float bv = __int_as_float(0x7f800000);
                float sv = __int_as_float(0x7f800000);
                int bi = 0;
                #pragma unroll
                for (int nt = 0; nt < 8; nt++) {
                    int k0 = col0 + wn * 64 + nt * 8 + (lane & 3) * 2;
                    float v0 = scn[k0]     - 2.0f * acc[mt][nt][h * 2];
                    float v1 = scn[k0 + 1] - 2.0f * acc[mt][nt][h * 2 + 1];
                    if (v0 < bv)      { sv = bv; bv = v0; bi = k0; }
                    else if (v0 < sv) { sv = v0; }
                    if (v1 < bv)      { sv = bv; bv = v1; bi = k0 + 1; }
                    else if (v1 < sv) { sv = v1; }
                }
                #pragma unroll
                for (int m = 1; m <= 2; m <<= 1) {
                    float b2 = __shfl_xor_sync(0xffffffffu, bv, m);
                    float s2 = __shfl_xor_sync(0xffffffffu, sv, m);
                    int   i2 = __shfl_xor_sync(0xffffffffu, bi, m);
                    if (b2 < bv || (b2 == bv && i2 < bi)) {
                        sv = fminf(bv, fminf(sv, s2)); bv = b2; bi = i2;
                    } else {
                        sv = fminf(fminf(sv, s2), b2);
                    }
                }
                if ((lane & 3) == 0) {
                    int row = wm * 32 + mt * 16 + h * 8 + (lane >> 2);
                    s_pb[wn * 128 + row] = bv;
                    s_ps[wn * 128 + row] = sv;
                    s_pi[wn * 128 + row] = bi;
                }
            }
        }
        __syncthreads();
        if (tid < 128) {
            float B = s_pb[tid], S = s_ps[tid]; int I = s_pi[tid];
            #pragma unroll
            for (int w = 1; w < 4; w++) {
                float b2 = s_pb[w * 128 + tid], s2 = s_ps[w * 128 + tid];
                int i2 = s_pi[w * 128 + tid];
                if (b2 < B) { S = fminf(B, fminf(S, s2)); B = b2; I = i2; }
                else        { S = fminf(fminf(S, s2), b2); }
            }
            float rB = s_best[tid], rS = s_sec[tid]; int rI = s_bidx[tid];
            if (B < rB) { rS = fminf(rB, fminf(rS, S)); rB = B; rI = I; }
            else        { rS = fminf(fminf(rS, S), B); }
            s_best[tid] = rB; s_sec[tid] = rS; s_bidx[tid] = rI;
        }
        __syncthreads();
    }

    if (tid < 128) {
        int n = row0 + tid;
        g_idx[n] = s_bidx[tid];
        if (s_sec[tid] - s_best[tid] < FIX_THRESH) {
            int slot = atomicAdd(&g_fix_count, 1);
            if (slot < 32768) g_fix_rows[slot] = n;
        }
    }
}

// ---------------------------------------------------------------------------
// Kernel 2: exact fp32 recheck of low-margin rows.
// Uses row-contiguous g_ct (L2-resident) with float4 dots.
// ---------------------------------------------------------------------------
__global__ void k_fixup(const float* __restrict__ x, const float* __restrict__ cnorm) {
    __shared__ float4 s_x[D_DIM / 4];
    __shared__ float rv[256];
    __shared__ int   rk[256];
    const int tid = threadIdx.x;
    int cnt = g_fix_count; if (cnt > 32768) cnt = 32768;

    for (int j = blockIdx.x; j < cnt; j += gridDim.x) {
        const int n = g_fix_rows[j];
        for (int d = tid; d < D_DIM / 4; d += 256)
            s_x[d] = ((const float4*)(x + (size_t)n * D_DIM))[d];
        __syncthreads();
        float best = __int_as_float(0x7f800000); int bk = 0;
        #pragma unroll 1
        for (int k0 = 0; k0 < K_DIM; k0 += 256) {
            int k = k0 + tid;
            const float4* cp = (const float4*)(g_ct + (size_t)k * D_DIM);
            float s = 0.f;
            #pragma unroll 8
            for (int d = 0; d < D_DIM / 4; d++) {
                float4 a = s_x[d], b = cp[d];
                s = fmaf(a.x, b.x, s); s = fmaf(a.y, b.y, s);
                s = fmaf(a.z, b.z, s); s = fmaf(a.w, b.w, s);
            }
            float val = cnorm[k] - 2.0f * s;
            if (val < best) { best = val; bk = k; }
        }
        rv[tid] = best; rk[tid] = bk;
        __syncthreads();
        for (int off = 128; off > 0; off >>= 1) {
            if (tid < off) {
                if (rv[tid + off] < rv[tid] ||
                    (rv[tid + off] == rv[tid] && rk[tid + off] < rk[tid])) {
                    rv[tid] = rv[tid + off]; rk[tid] = rk[tid + off];
                }
            }
            __syncthreads();
        }
        if (tid == 0) g_idx[n] = rk[0];
        __syncthreads();
    }
}

// ---------------------------------------------------------------------------
// Kernel 3: gather — out[n,:] = CT[idx[n],:]; 16 rows per block.
// ---------------------------------------------------------------------------
__global__ void k_gather(float* __restrict__ out) {
    const int r0 = blockIdx.x * 16;
    const int t = threadIdx.x;
    #pragma unroll
    for (int r = 0; r < 16; r++) {
        const int n = r0 + r;
        const int k = g_idx[n];
        const float4* src = (const float4*)(g_ct + (size_t)k * D_DIM);
        float4* dst = (float4*)(out + (size_t)n * D_DIM);
        dst[t] = src[t];
    }
}

extern "C" void kernel_launch(void* const* d_in, const int* in_sizes, int n_in,
                              void* d_out, int out_size) {
    const float* x     = (const float*)d_in[0];
    const float* C     = (const float*)d_in[1];
    const float* Cnorm = (const float*)d_in[2];
    float* out = (float*)d_out;

    static bool attr_set = false;
    if (!attr_set) {
        cudaFuncSetAttribute(k_main, cudaFuncAttributeMaxDynamicSharedMemorySize, SMEM_TOTAL);
        attr_set = true;
    }

    k_prep<<<(K_DIM * D_DIM) / 256, 256>>>(C);
    k_main<<<N_ROWS / 128, 512, SMEM_TOTAL>>>(x, Cnorm);
    k_fixup<<<512, 256>>>(x, Cnorm);
    k_gather<<<N_ROWS / 16, 192>>>(out);
}

// round 8
// speedup vs baseline: 1.7969x; 1.0038x over previous
#include <cuda_runtime.h>
#include <cuda_fp16.h>
#include <cstdint>

#define N_ROWS 262144
#define D_DIM  768
#define K_DIM  1024

// ---------------- device scratch ----------------
__device__ float  g_ct [K_DIM * D_DIM];   // fp32 C^T (gather + exact fixup)
__device__ __half g_bhi[K_DIM * D_DIM];   // fp16 C^T (K-major)
__device__ int    g_idx[N_ROWS];
__device__ int    g_fix_count;
__device__ int    g_fix_rows[32768];

// ---------------- helpers ----------------
__device__ __forceinline__ uint32_t smem_u32(const void* p) {
    uint32_t a;
    asm("{ .reg .u64 t; cvta.to.shared.u64 t, %1; cvt.u32.u64 %0, t; }" : "=r"(a) : "l"(p));
    return a;
}
__device__ __forceinline__ void cpa16(uint32_t dst, const void* src) {
    asm volatile("{ .reg .u64 p; cvta.to.global.u64 p, %1; cp.async.cg.shared.global [%0], [p], 16; }"
                 :: "r"(dst), "l"(src));
}
__device__ __forceinline__ void ldsm4(uint32_t* r, uint32_t a) {
    asm volatile("ldmatrix.sync.aligned.m8n8.x4.shared.b16 {%0,%1,%2,%3}, [%4];"
                 : "=r"(r[0]), "=r"(r[1]), "=r"(r[2]), "=r"(r[3]) : "r"(a));
}
__device__ __forceinline__ void mma16816(float* c, const uint32_t* a, uint32_t b0, uint32_t b1) {
    asm volatile("mma.sync.aligned.m16n8k16.row.col.f32.f16.f16.f32 "
                 "{%0,%1,%2,%3},{%4,%5,%6,%7},{%8,%9},{%0,%1,%2,%3};"
                 : "+f"(c[0]), "+f"(c[1]), "+f"(c[2]), "+f"(c[3])
                 : "r"(a[0]), "r"(a[1]), "r"(a[2]), "r"(a[3]), "r"(b0), "r"(b1));
}
__device__ __forceinline__ uint32_t packh2(float a, float b) {
    __half2 t = __floats2half2_rn(a, b);
    return *reinterpret_cast<uint32_t*>(&t);
}

#define FIX_THRESH 0.30f

// ---------------- smem layout (dynamic) ----------------
// CTA: 64 rows x 256-col chunks, 256 threads, 2 CTAs/SM.
#define SM_CN   0        // 1024 f32
#define SM_PB   4096     // 4 x 64 f32 partials
#define SM_PS   5120
#define SM_PI   6144
#define SM_BEST 7168     // 64 f32
#define SM_SEC  7424
#define SM_BIDX 7680
#define SM_STG  8192
#define STG_BYTES 25600  // per stage: A 64x80B + B 256x80B
#define A_HI 0
#define B_HI 5120
#define SMEM_TOTAL (8192 + 2 * 25600)    // 59392 -> 2 CTAs = 118784 B/SM

// ---------------------------------------------------------------------------
// Kernel 0: C -> fp32 C^T + fp16 C^T; zero fixup counter
// ---------------------------------------------------------------------------
__global__ void k_prep(const float* __restrict__ C) {
    int idx = blockIdx.x * 256 + threadIdx.x;    // idx = d*1024 + k
    if (idx == 0) g_fix_count = 0;
    int d = idx >> 10, k = idx & 1023;
    float v = C[idx];
    size_t o = (size_t)k * D_DIM + d;
    g_ct[o] = v; g_bhi[o] = __float2half_rn(v);
}

// ---------------------------------------------------------------------------
// Kernel 1: fp16 mma.sync GEMM + argmin. 64 rows/CTA, 256 threads,
// warp grid 2x4, warp tile 32x64, occupancy 2 CTAs/SM.
// ---------------------------------------------------------------------------
__global__ void __launch_bounds__(256, 2)
k_main(const float* __restrict__ x, const float* __restrict__ cnorm) {
    extern __shared__ char sm[];
    const uint32_t sbase = smem_u32(sm);
    const int tid  = threadIdx.x;
    const int lane = tid & 31, warp = tid >> 5;
    const int wm = warp >> 2, wn = warp & 3;      // 2 x 4
    const int row0 = blockIdx.x * 64;

    float* scn    = (float*)(sm + SM_CN);
    float* s_pb   = (float*)(sm + SM_PB);
    float* s_ps   = (float*)(sm + SM_PS);
    int*   s_pi   = (int*)  (sm + SM_PI);
    float* s_best = (float*)(sm + SM_BEST);
    float* s_sec  = (float*)(sm + SM_SEC);
    int*   s_bidx = (int*)  (sm + SM_BIDX);

    for (int i = tid; i < K_DIM; i += 256) scn[i] = cnorm[i];
    if (tid < 64) {
        s_best[tid] = __int_as_float(0x7f800000);
        s_sec[tid]  = __int_as_float(0x7f800000);
        s_bidx[tid] = 0;
    }
    __syncthreads();

    // A fill mapping: thread -> (row ar = tid>>2, 8 floats at col (tid&3)*8)
    const int ar = tid >> 2, aq = tid & 3;
    const float* xp = x + (size_t)(row0 + ar) * D_DIM + aq * 8;
    const uint32_t a_sts = (uint32_t)(ar * 80 + aq * 16);

    // ldmatrix lane base offsets (proven fragment maps)
    const uint32_t a_ld = (uint32_t)((wm * 32 + (lane & 15)) * 80 + (lane >> 4) * 16);
    const uint32_t b_ld = (uint32_t)((wn * 64 + (lane & 7) + ((lane & 16) ? 8 : 0)) * 80
                                     + ((lane >> 3) & 1) * 16);

    for (int cc = 0; cc < 4; cc++) {
        const int col0 = cc * 256;
        float acc[2][8][4];
        #pragma unroll
        for (int mt = 0; mt < 2; mt++)
            #pragma unroll
            for (int nt = 0; nt < 8; nt++)
                #pragma unroll
                for (int c = 0; c < 4; c++) acc[mt][nt][c] = 0.f;

        // B source pointer for this thread within the chunk (advances by 32 d each iter)
        const int bn = tid >> 2, bq = tid & 3;   // with 4 iters of +256 threads
        // ---- prologue: fill stage 0 ----
        {
            #pragma unroll
            for (int i = 0; i < 4; i++) {
                int idx = tid + i * 256;
                int n = idx >> 2, q = idx & 3;
                cpa16(sbase + SM_STG + B_HI + n * 80 + q * 16,
                      g_bhi + (size_t)(col0 + n) * D_DIM + q * 8);
            }
            asm volatile("cp.async.commit_group;");
            float4 v0 = *(const float4*)(xp);
            float4 v1 = *(const float4*)(xp + 4);
            uint32_t h[4] = { packh2(v0.x, v0.y), packh2(v0.z, v0.w),
                              packh2(v1.x, v1.y), packh2(v1.z, v1.w) };
            asm volatile("st.shared.v4.b32 [%0], {%1,%2,%3,%4};"
                         :: "r"(sbase + SM_STG + A_HI + a_sts),
                            "r"(h[0]), "r"(h[1]), "r"(h[2]), "r"(h[3]));
        }
        (void)bn; (void)bq;

        for (int dc = 0; dc < 24; dc++) {
            const int buf = dc & 1;
            asm volatile("cp.async.wait_group 0;");
            __syncthreads();

            float4 nv0, nv1;
            const bool more = (dc < 23);
            if (more) {
                const int d0n = (dc + 1) * 32;
                #pragma unroll
                for (int i = 0; i < 4; i++) {
                    int idx = tid + i * 256;
                    int n = idx >> 2, q = idx & 3;
                    cpa16(sbase + SM_STG + (buf ^ 1) * STG_BYTES + B_HI + n * 80 + q * 16,
                          g_bhi + (size_t)(col0 + n) * D_DIM + d0n + q * 8);
                }
                asm volatile("cp.async.commit_group;");
                nv0 = *(const float4*)(xp + d0n);
                nv1 = *(const float4*)(xp + d0n + 4);
            }

            // ---- compute: 2 k16-steps x 16 mmas ----
            const uint32_t stg = sbase + SM_STG + buf * STG_BYTES;
            const uint32_t ab = stg + A_HI + a_ld;
            const uint32_t bb = stg + B_HI + b_ld;
            #pragma unroll
            for (int ks = 0; ks < 2; ks++) {
                uint32_t afr[2][4];
                ldsm4(afr[0], ab + ks * 32);
                ldsm4(afr[1], ab + 1280 + ks * 32);          // +16 rows * 80B
                uint32_t bfr[4][4];
                #pragma unroll
                for (int bt = 0; bt < 4; bt++)
                    ldsm4(bfr[bt], bb + bt * 1280 + ks * 32);
                #pragma unroll
                for (int mt = 0; mt < 2; mt++)
                    #pragma unroll
                    for (int nt = 0; nt < 8; nt++)
                        mma16816(acc[mt][nt], afr[mt],
                                 bfr[nt >> 1][(nt & 1) * 2],
                                 bfr[nt >> 1][(nt & 1) * 2 + 1]);
            }

            if (more) {
                uint32_t h[4] = { packh2(nv0.x, nv0.y), packh2(nv0.z, nv0.w),
                                  packh2(nv1.x, nv1.y), packh2(nv1.z, nv1.w) };
                asm volatile("st.shared.v4.b32 [%0], {%1,%2,%3,%4};"
                             :: "r"(sbase + SM_STG + (buf ^ 1) * STG_BYTES + A_HI + a_sts),
                                "r"(h[0]), "r"(h[1]), "r"(h[2]), "r"(h[3]));
            }
        }

        // ---- epilogue for this 256-col chunk (best + second + index) ----
        #pragma unroll
        for (int mt = 0; mt < 2; mt++) {
            #pragma unroll
            for (int h = 0; h < 2; h++) {
                float bv = __int_as_float(0x7f800000);
                float sv = __int_as_float(0x7f800000);
                int bi = 0;
                #pragma unroll
                for (int nt = 0; nt < 8; nt++) {
                    int k0 = col0 + wn * 64 + nt * 8 + (lane & 3) * 2;
                    float v0 = scn[k0]     - 2.0f * acc[mt][nt][h * 2];
                    float v1 = scn[k0 + 1] - 2.0f * acc[mt][nt][h * 2 + 1];
                    if (v0 < bv)      { sv = bv; bv = v0; bi = k0; }
                    else if (v0 < sv) { sv = v0; }
                    if (v1 < bv)      { sv = bv; bv = v1; bi = k0 + 1; }
                    else if (v1 < sv) { sv = v1; }
                }
                #pragma unroll
                for (int m = 1; m <= 2; m <<= 1) {
                    float b2 = __shfl_xor_sync(0xffffffffu, bv, m);
                    float s2 = __shfl_xor_sync(0xffffffffu, sv, m);
                    int   i2 = __shfl_xor_sync(0xffffffffu, bi, m);
                    if (b2 < bv || (b2 == bv && i2 < bi)) {
                        sv = fminf(bv, fminf(sv, s2)); bv = b2; bi = i2;
                    } else {
                        sv = fminf(fminf(sv, s2), b2);
                    }
                }
                if ((lane & 3) == 0) {
                    int row = wm * 32 + mt * 16 + h * 8 + (lane >> 2);   // 0..63
                    s_pb[wn * 64 + row] = bv;
                    s_ps[wn * 64 + row] = sv;
                    s_pi[wn * 64 + row] = bi;
                }
            }
        }
        __syncthreads();
        if (tid < 64) {
            float B = s_pb[tid], S = s_ps[tid]; int I = s_pi[tid];
            #pragma unroll
            for (int w = 1; w < 4; w++) {
                float b2 = s_pb[w * 64 + tid], s2 = s_ps[w * 64 + tid];
                int i2 = s_pi[w * 64 + tid];
                if (b2 < B) { S = fminf(B, fminf(S, s2)); B = b2; I = i2; }
                else        { S = fminf(fminf(S, s2), b2); }
            }
            float rB = s_best[tid], rS = s_sec[tid]; int rI = s_bidx[tid];
            if (B < rB) { rS = fminf(rB, fminf(rS, S)); rB = B; rI = I; }
            else        { rS = fminf(fminf(rS, S), B); }
            s_best[tid] = rB; s_sec[tid] = rS; s_bidx[tid] = rI;
        }
        __syncthreads();
    }

    if (tid < 64) {
        int n = row0 + tid;
        g_idx[n] = s_bidx[tid];
        if (s_sec[tid] - s_best[tid] < FIX_THRESH) {
            int slot = atomicAdd(&g_fix_count, 1);
            if (slot < 32768) g_fix_rows[slot] = n;
        }
    }
}

// ---------------------------------------------------------------------------
// Kernel 2: exact fp32 recheck of low-margin rows (g_ct row-contiguous, L2-hot)
// ---------------------------------------------------------------------------
__global__ void k_fixup(const float* __restrict__ x, const float* __restrict__ cnorm) {
    __shared__ float4 s_x[D_DIM / 4];
    __shared__ float rv[256];
    __shared__ int   rk[256];
    const int tid = threadIdx.x;
    int cnt = g_fix_count; if (cnt > 32768) cnt = 32768;

    for (int j = blockIdx.x; j < cnt; j += gridDim.x) {
        const int n = g_fix_rows[j];
        for (int d = tid; d < D_DIM / 4; d += 256)
            s_x[d] = ((const float4*)(x + (size_t)n * D_DIM))[d];
        __syncthreads();
        float best = __int_as_float(0x7f800000); int bk = 0;
        #pragma unroll 1
        for (int k0 = 0; k0 < K_DIM; k0 += 256) {
            int k = k0 + tid;
            const float4* cp = (const float4*)(g_ct + (size_t)k * D_DIM);
            float s = 0.f;
            #pragma unroll 8
            for (int d = 0; d < D_DIM / 4; d++) {
                float4 a = s_x[d], b = cp[d];
                s = fmaf(a.x, b.x, s); s = fmaf(a.y, b.y, s);
                s = fmaf(a.z, b.z, s); s = fmaf(a.w, b.w, s);
            }
            float val = cnorm[k] - 2.0f * s;
            if (val < best) { best = val; bk = k; }
        }
        rv[tid] = best; rk[tid] = bk;
        __syncthreads();
        for (int off = 128; off > 0; off >>= 1) {
            if (tid < off) {
                if (rv[tid + off] < rv[tid] ||
                    (rv[tid + off] == rv[tid] && rk[tid + off] < rk[tid])) {
                    rv[tid] = rv[tid + off]; rk[tid] = rk[tid + off];
                }
            }
            __syncthreads();
        }
        if (tid == 0) g_idx[n] = rk[0];
        __syncthreads();
    }
}

// ---------------------------------------------------------------------------
// Kernel 3: gather — out[n,:] = CT[idx[n],:]; 16 rows per block.
// ---------------------------------------------------------------------------
__global__ void k_gather(float* __restrict__ out) {
    const int r0 = blockIdx.x * 16;
    const int t = threadIdx.x;
    #pragma unroll
    for (int r = 0; r < 16; r++) {
        const int n = r0 + r;
        const int k = g_idx[n];
        const float4* src = (const float4*)(g_ct + (size_t)k * D_DIM);
        float4* dst = (float4*)(out + (size_t)n * D_DIM);
        dst[t] = src[t];
    }
}

extern "C" void kernel_launch(void* const* d_in, const int* in_sizes, int n_in,
                              void* d_out, int out_size) {
    const float* x     = (const float*)d_in[0];
    const float* C     = (const float*)d_in[1];
    const float* Cnorm = (const float*)d_in[2];
    float* out = (float*)d_out;

    static bool attr_set = false;
    if (!attr_set) {
        cudaFuncSetAttribute(k_main, cudaFuncAttributeMaxDynamicSharedMemorySize, SMEM_TOTAL);
        attr_set = true;
    }

    k_prep<<<(K_DIM * D_DIM) / 256, 256>>>(C);
    k_main<<<N_ROWS / 64, 256, SMEM_TOTAL>>>(x, Cnorm);
    k_fixup<<<512, 256>>>(x, Cnorm);
    k_gather<<<N_ROWS / 16, 192>>>(out);
}

// round 9
// speedup vs baseline: 1.8022x; 1.0029x over previous
#include <cuda_runtime.h>
#include <cuda_fp16.h>
#include <cstdint>

#define N_ROWS 262144
#define D_DIM  768
#define K_DIM  1024

// ---------------- device scratch ----------------
__device__ float  g_ct [K_DIM * D_DIM];   // fp32 C^T (gather + exact fixup)
__device__ __half g_bhi[K_DIM * D_DIM];   // fp16 C^T (K-major)
__device__ int    g_idx[N_ROWS];
__device__ int    g_fix_count;
__device__ int    g_fix_rows[32768];

// ---------------- helpers ----------------
__device__ __forceinline__ uint32_t smem_u32(const void* p) {
    uint32_t a;
    asm("{ .reg .u64 t; cvta.to.shared.u64 t, %1; cvt.u32.u64 %0, t; }" : "=r"(a) : "l"(p));
    return a;
}
__device__ __forceinline__ void cpa16(uint32_t dst, const void* src) {
    asm volatile("{ .reg .u64 p; cvta.to.global.u64 p, %1; cp.async.cg.shared.global [%0], [p], 16; }"
                 :: "r"(dst), "l"(src));
}
__device__ __forceinline__ void ldsm4(uint32_t* r, uint32_t a) {
    asm volatile("ldmatrix.sync.aligned.m8n8.x4.shared.b16 {%0,%1,%2,%3}, [%4];"
                 : "=r"(r[0]), "=r"(r[1]), "=r"(r[2]), "=r"(r[3]) : "r"(a));
}
__device__ __forceinline__ void mma16816(float* c, const uint32_t* a, uint32_t b0, uint32_t b1) {
    asm volatile("mma.sync.aligned.m16n8k16.row.col.f32.f16.f16.f32 "
                 "{%0,%1,%2,%3},{%4,%5,%6,%7},{%8,%9},{%0,%1,%2,%3};"
                 : "+f"(c[0]), "+f"(c[1]), "+f"(c[2]), "+f"(c[3])
                 : "r"(a[0]), "r"(a[1]), "r"(a[2]), "r"(a[3]), "r"(b0), "r"(b1));
}
__device__ __forceinline__ uint32_t packh2(float a, float b) {
    __half2 t = __floats2half2_rn(a, b);
    return *reinterpret_cast<uint32_t*>(&t);
}

#define FIX_THRESH 0.30f

// ---------------- smem layout ----------------
// 128 rows/CTA, 512 threads, 3 stages, d-chunk 64, 128B swizzled rows.
#define SM_CN   0        // 1024 f32
#define SM_PB   4096     // 4 x 128 f32
#define SM_PS   6144
#define SM_PI   8192
#define SM_BEST 10240
#define SM_SEC  10752
#define SM_BIDX 11264
#define SM_STG  12288
#define A_OFF   0        // 128 x 128B = 16 KB
#define B_OFF   16384    // 256 x 128B = 32 KB
#define STG_BYTES 49152
#define N_STAGE 3
#define SMEM_TOTAL (12288 + 3 * 49152)   // 159744

#define TOT_IT 48        // 4 chunks x 12 d-iters

// ---------------------------------------------------------------------------
// Kernel 0: C -> fp32 C^T + fp16 C^T; zero fixup counter
// ---------------------------------------------------------------------------
__global__ void k_prep(const float* __restrict__ C) {
    int idx = blockIdx.x * 256 + threadIdx.x;    // idx = d*1024 + k
    if (idx == 0) g_fix_count = 0;
    int d = idx >> 10, k = idx & 1023;
    float v = C[idx];
    size_t o = (size_t)k * D_DIM + d;
    g_ct[o] = v; g_bhi[o] = __float2half_rn(v);
}

// ---------------------------------------------------------------------------
// Kernel 1: fp16 mma.sync GEMM + argmin. 128 rows, 512 thr, warp grid 4x4,
// warp tile 32x64, 3-stage cp.async pipeline, d-chunk 64.
// ---------------------------------------------------------------------------
__global__ void __launch_bounds__(512)
k_main(const float* __restrict__ x, const float* __restrict__ cnorm) {
    extern __shared__ char sm[];
    const uint32_t sbase = smem_u32(sm);
    const int tid  = threadIdx.x;
    const int lane = tid & 31, warp = tid >> 5;
    const int wm = warp >> 2, wn = warp & 3;
    const int row0 = blockIdx.x * 128;

    float* scn    = (float*)(sm + SM_CN);
    float* s_pb   = (float*)(sm + SM_PB);
    float* s_ps   = (float*)(sm + SM_PS);
    int*   s_pi   = (int*)  (sm + SM_PI);
    float* s_best = (float*)(sm + SM_BEST);
    float* s_sec  = (float*)(sm + SM_SEC);
    int*   s_bidx = (int*)  (sm + SM_BIDX);

    for (int i = tid; i < K_DIM; i += 512) scn[i] = cnorm[i];
    if (tid < 128) {
        s_best[tid] = __int_as_float(0x7f800000);
        s_sec[tid]  = __int_as_float(0x7f800000);
        s_bidx[tid] = 0;
    }
    __syncthreads();

    // A map: thread -> (row ar = tid>>2, 16 cols at (tid&3)*16)
    const int ar = tid >> 2, aq = tid & 3;
    const float* xrow = x + (size_t)(row0 + ar) * D_DIM + aq * 16;
    const int akey_sts = ar & 7;

    // ldmatrix lane bases (row*128), swizzle key = lane&7 for both A and B
    const uint32_t a_row = (uint32_t)((wm * 32 + (lane & 15)) * 128);
    const uint32_t b_row = (uint32_t)((wn * 64 + (lane & 7) + ((lane & 16) ? 8 : 0)) * 128);
    const int key = lane & 7;
    const int a_qs = (lane >> 4);        // 0/1
    const int b_qs = (lane >> 3) & 1;    // 0/1

    float acc[2][8][4];
    #pragma unroll
    for (int mt = 0; mt < 2; mt++)
        #pragma unroll
        for (int nt = 0; nt < 8; nt++)
            #pragma unroll
            for (int c = 0; c < 4; c++) acc[mt][nt][c] = 0.f;

    // ---- B fill: iteration t -> 256 rows x 64 d (32 KB), 4 cp.async/thread
    auto bfill = [&](int t, int stage) {
        const __half* src = g_bhi + (size_t)((t / 12) * 256) * D_DIM + (t % 12) * 64;
        const uint32_t bb = sbase + SM_STG + stage * STG_BYTES + B_OFF;
        #pragma unroll
        for (int i = 0; i < 4; i++) {
            int u = tid + i * 512;
            int n = u >> 3, q = u & 7;
            cpa16(bb + n * 128 + ((q ^ (n & 7)) << 4), src + (size_t)n * D_DIM + q * 8);
        }
        asm volatile("cp.async.commit_group;");
    };
    // ---- A store from 16 held floats (converted here), into stage
    auto asts = [&](const float4* av, int stage) {
        uint32_t h[8];
        #pragma unroll
        for (int j = 0; j < 4; j++) {
            h[2*j]   = packh2(av[j].x, av[j].y);
            h[2*j+1] = packh2(av[j].z, av[j].w);
        }
        uint32_t da = sbase + SM_STG + stage * STG_BYTES + A_OFF + ar * 128;
        uint32_t o0 = (uint32_t)(((2 * aq)     ^ akey_sts) << 4);
        uint32_t o1 = (uint32_t)(((2 * aq + 1) ^ akey_sts) << 4);
        asm volatile("st.shared.v4.b32 [%0], {%1,%2,%3,%4};"
                     :: "r"(da + o0), "r"(h[0]), "r"(h[1]), "r"(h[2]), "r"(h[3]));
        asm volatile("st.shared.v4.b32 [%0], {%1,%2,%3,%4};"
                     :: "r"(da + o1), "r"(h[4]), "r"(h[5]), "r"(h[6]), "r"(h[7]));
    };

    float4 av[4];
    // ---- prologue ----
    bfill(0, 0);                                   // G0
    {   // A(0) direct
        const float* p = xrow;                     // t=0 -> d0=0
        float4 t0[4] = { *(const float4*)p, *(const float4*)(p+4),
                         *(const float4*)(p+8), *(const float4*)(p+12) };
        asts(t0, 0);
    }
    bfill(1, 1);                                   // G1
    {   // load A(1) into av
        const float* p = xrow + 64;
        av[0] = *(const float4*)p;   av[1] = *(const float4*)(p+4);
        av[2] = *(const float4*)(p+8); av[3] = *(const float4*)(p+12);
    }

    for (int s = 0; s < TOT_IT; s++) {
        const int st = s % N_STAGE;
        // 1. STS A(s+1) from held regs
        if (s + 1 < TOT_IT) asts(av, (s + 1) % N_STAGE);
        // 2. issue LDG A(s+2)  (lands during wait + compute)
        if (s + 2 < TOT_IT) {
            const float* p = xrow + ((s + 2) % 12) * 64;
            av[0] = *(const float4*)p;     av[1] = *(const float4*)(p+4);
            av[2] = *(const float4*)(p+8); av[3] = *(const float4*)(p+12);
        }
        // 3. wait for B(s) (newest group G_{s+1} may still fly)
        asm volatile("cp.async.wait_group 1;");
        __syncthreads();
        // 4. refill freed stage with B(s+2)
        if (s + 2 < TOT_IT) bfill(s + 2, (s + 2) % N_STAGE);

        // 5. compute on stage st: 4 k16-steps x 16 mmas
        const uint32_t ab = sbase + SM_STG + st * STG_BYTES + A_OFF + a_row;
        const uint32_t bb = sbase + SM_STG + st * STG_BYTES + B_OFF + b_row;
        #pragma unroll
        for (int ks = 0; ks < 4; ks++) {
            uint32_t afr[2][4];
            const uint32_t aoff = (uint32_t)(((ks * 2 + a_qs) ^ key) << 4);
            ldsm4(afr[0], ab + aoff);
            ldsm4(afr[1], ab + 16 * 128 + aoff);
            uint32_t bfr[4][4];
            const uint32_t boff = (uint32_t)(((ks * 2 + b_qs) ^ key) << 4);
            #pragma unroll
            for (int bt = 0; bt < 4; bt++)
                ldsm4(bfr[bt], bb + bt * 16 * 128 + boff);
            #pragma unroll
            for (int mt = 0; mt < 2; mt++)
                #pragma unroll
                for (int nt = 0; nt < 8; nt++)
                    mma16816(acc[mt][nt], afr[mt],
                             bfr[nt >> 1][(nt & 1) * 2],
                             bfr[nt >> 1][(nt & 1) * 2 + 1]);
        }

        // 6. chunk boundary: epilogue + reset acc
        if ((s % 12) == 11) {
            const int col0 = (s / 12) * 256;
            #pragma unroll
            for (int mt = 0; mt < 2; mt++) {
                #pragma unroll
                for (int h = 0; h < 2; h++) {
                    float bv = __int_as_float(0x7f800000);
                    float sv = __int_as_float(0x7f800000);
                    int bi = 0;
                    #pragma unroll
                    for (int nt = 0; nt < 8; nt++) {
                        int k0 = col0 + wn * 64 + nt * 8 + (lane & 3) * 2;
                        float v0 = scn[k0]     - 2.0f * acc[mt][nt][h * 2];
                        float v1 = scn[k0 + 1] - 2.0f * acc[mt][nt][h * 2 + 1];
                        if (v0 < bv)      { sv = bv; bv = v0; bi = k0; }
                        else if (v0 < sv) { sv = v0; }
                        if (v1 < bv)      { sv = bv; bv = v1; bi = k0 + 1; }
                        else if (v1 < sv) { sv = v1; }
                    }
                    #pragma unroll
                    for (int m = 1; m <= 2; m <<= 1) {
                        float b2 = __shfl_xor_sync(0xffffffffu, bv, m);
                        float s2 = __shfl_xor_sync(0xffffffffu, sv, m);
                        int   i2 = __shfl_xor_sync(0xffffffffu, bi, m);
                        if (b2 < bv || (b2 == bv && i2 < bi)) {
                            sv = fminf(bv, fminf(sv, s2)); bv = b2; bi = i2;
                        } else {
                            sv = fminf(fminf(sv, s2), b2);
                        }
                    }
                    if ((lane & 3) == 0) {
                        int row = wm * 32 + mt * 16 + h * 8 + (lane >> 2);
                        s_pb[wn * 128 + row] = bv;
                        s_ps[wn * 128 + row] = sv;
                        s_pi[wn * 128 + row] = bi;
                    }
                }
            }
            __syncthreads();
            if (tid < 128) {
                float B = s_pb[tid], S = s_ps[tid]; int I = s_pi[tid];
                #pragma unroll
                for (int w = 1; w < 4; w++) {
                    float b2 = s_pb[w * 128 + tid], s2 = s_ps[w * 128 + tid];
                    int i2 = s_pi[w * 128 + tid];
                    if (b2 < B) { S = fminf(B, fminf(S, s2)); B = b2; I = i2; }
                    else        { S = fminf(fminf(S, s2), b2); }
                }
                float rB = s_best[tid], rS = s_sec[tid]; int rI = s_bidx[tid];
                if (B < rB) { rS = fminf(rB, fminf(rS, S)); rB = B; rI = I; }
                else        { rS = fminf(fminf(rS, S), B); }
                s_best[tid] = rB; s_sec[tid] = rS; s_bidx[tid] = rI;
            }
            __syncthreads();
            #pragma unroll
            for (int mt = 0; mt < 2; mt++)
                #pragma unroll
                for (int nt = 0; nt < 8; nt++)
                    #pragma unroll
                    for (int c = 0; c < 4; c++) acc[mt][nt][c] = 0.f;
        }
    }

    if (tid < 128) {
        int n = row0 + tid;
        g_idx[n] = s_bidx[tid];
        if (s_sec[tid] - s_best[tid] < FIX_THRESH) {
            int slot = atomicAdd(&g_fix_count, 1);
            if (slot < 32768) g_fix_rows[slot] = n;
        }
    }
}

// ---------------------------------------------------------------------------
// Kernel 2: exact fp32 recheck of low-margin rows (g_ct row-contiguous, L2-hot)
// ---------------------------------------------------------------------------
__global__ void k_fixup(const float* __restrict__ x, const float* __restrict__ cnorm) {
    __shared__ float4 s_x[D_DIM / 4];
    __shared__ float rv[256];
    __shared__ int   rk[256];
    const int tid = threadIdx.x;
    int cnt = g_fix_count; if (cnt > 32768) cnt = 32768;

    for (int j = blockIdx.x; j < cnt; j += gridDim.x) {
        const int n = g_fix_rows[j];
        for (int d = tid; d < D_DIM / 4; d += 256)
            s_x[d] = ((const float4*)(x + (size_t)n * D_DIM))[d];
        __syncthreads();
        float best = __int_as_float(0x7f800000); int bk = 0;
        #pragma unroll 1
        for (int k0 = 0; k0 < K_DIM; k0 += 256) {
            int k = k0 + tid;
            const float4* cp = (const float4*)(g_ct + (size_t)k * D_DIM);
            float s = 0.f;
            #pragma unroll 8
            for (int d = 0; d < D_DIM / 4; d++) {
                float4 a = s_x[d], b = cp[d];
                s = fmaf(a.x, b.x, s); s = fmaf(a.y, b.y, s);
                s = fmaf(a.z, b.z, s); s = fmaf(a.w, b.w, s);
            }
            float val = cnorm[k] - 2.0f * s;
            if (val < best) { best = val; bk = k; }
        }
        rv[tid] = best; rk[tid] = bk;
        __syncthreads();
        for (int off = 128; off > 0; off >>= 1) {
            if (tid < off) {
                if (rv[tid + off] < rv[tid] ||
                    (rv[tid + off] == rv[tid] && rk[tid + off] < rk[tid])) {
                    rv[tid] = rv[tid + off]; rk[tid] = rk[tid + off];
                }
            }
            __syncthreads();
        }
        if (tid == 0) g_idx[n] = rk[0];
        __syncthreads();
    }
}

// ---------------------------------------------------------------------------
// Kernel 3: gather — out[n,:] = CT[idx[n],:]; 16 rows per block.
// ---------------------------------------------------------------------------
__global__ void k_gather(float* __restrict__ out) {
    const int r0 = blockIdx.x * 16;
    const int t = threadIdx.x;
    #pragma unroll
    for (int r = 0; r < 16; r++) {
        const int n = r0 + r;
        const int k = g_idx[n];
        const float4* src = (const float4*)(g_ct + (size_t)k * D_DIM);
        float4* dst = (float4*)(out + (size_t)n * D_DIM);
        dst[t] = src[t];
    }
}

extern "C" void kernel_launch(void* const* d_in, const int* in_sizes, int n_in,
                              void* d_out, int out_size) {
    const float* x     = (const float*)d_in[0];
    const float* C     = (const float*)d_in[1];
    const float* Cnorm = (const float*)d_in[2];
    float* out = (float*)d_out;

    static bool attr_set = false;
    if (!attr_set) {
        cudaFuncSetAttribute(k_main, cudaFuncAttributeMaxDynamicSharedMemorySize, SMEM_TOTAL);
        attr_set = true;
    }

    k_prep<<<(K_DIM * D_DIM) / 256, 256>>>(C);
    k_main<<<N_ROWS / 128, 512, SMEM_TOTAL>>>(x, Cnorm);
    k_fixup<<<512, 256>>>(x, Cnorm);
    k_gather<<<N_ROWS / 16, 192>>>(out);
}

// round 10
// speedup vs baseline: 1.8615x; 1.0329x over previous
#include <cuda_runtime.h>
#include <cuda_bf16.h>
#include <cstdint>

#define N_ROWS 262144
#define D_DIM  768
#define K_DIM  1024

// ---------------- device scratch ----------------
__device__ float         g_ct [K_DIM * D_DIM];   // fp32 C^T (gather + exact fixup)
__device__ __nv_bfloat16 g_bhi[K_DIM * D_DIM];   // bf16 C^T (K-major)
__device__ int           g_idx[N_ROWS];
__device__ int           g_fix_count;
__device__ int           g_fix_rows[32768];

// ---------------- helpers ----------------
__device__ __forceinline__ uint32_t smem_u32(const void* p) {
    uint32_t a;
    asm("{ .reg .u64 t; cvta.to.shared.u64 t, %1; cvt.u32.u64 %0, t; }" : "=r"(a) : "l"(p));
    return a;
}
__device__ __forceinline__ void cpa16(uint32_t dst, const void* src) {
    asm volatile("{ .reg .u64 p; cvta.to.global.u64 p, %1; cp.async.cg.shared.global [%0], [p], 16; }"
                 :: "r"(dst), "l"(src));
}
__device__ __forceinline__ void ldsm4(uint32_t* r, uint32_t a) {
    asm volatile("ldmatrix.sync.aligned.m8n8.x4.shared.b16 {%0,%1,%2,%3}, [%4];"
                 : "=r"(r[0]), "=r"(r[1]), "=r"(r[2]), "=r"(r[3]) : "r"(a));
}
__device__ __forceinline__ void mma16816(float* c, const uint32_t* a, uint32_t b0, uint32_t b1) {
    asm volatile("mma.sync.aligned.m16n8k16.row.col.f32.bf16.bf16.f32 "
                 "{%0,%1,%2,%3},{%4,%5,%6,%7},{%8,%9},{%0,%1,%2,%3};"
                 : "+f"(c[0]), "+f"(c[1]), "+f"(c[2]), "+f"(c[3])
                 : "r"(a[0]), "r"(a[1]), "r"(a[2]), "r"(a[3]), "r"(b0), "r"(b1));
}
__device__ __forceinline__ uint32_t packb2(float a, float b) {
    __nv_bfloat162 t = __floats2bfloat162_rn(a, b);
    return *reinterpret_cast<uint32_t*>(&t);
}

#define FIX_THRESH 0.87f
#define FIX_CAP    32768

// ---------------- smem layout ----------------
// 128 rows/CTA, 512 threads, 3 stages, d-chunk 64, 128B swizzled rows.
#define SM_CN   0        // 1024 f32
#define SM_PB   4096     // 4 x 128 f32
#define SM_PS   6144
#define SM_PI   8192
#define SM_BEST 10240
#define SM_SEC  10752
#define SM_BIDX 11264
#define SM_STG  12288
#define A_OFF   0        // 128 x 128B = 16 KB
#define B_OFF   16384    // 256 x 128B = 32 KB
#define STG_BYTES 49152
#define N_STAGE 3
#define SMEM_TOTAL (12288 + 3 * 49152)   // 159744

#define TOT_IT 48        // 4 chunks x 12 d-iters

// ---------------------------------------------------------------------------
// Kernel 0: C -> fp32 C^T + bf16 C^T; zero fixup counter
// ---------------------------------------------------------------------------
__global__ void k_prep(const float* __restrict__ C) {
    int idx = blockIdx.x * 256 + threadIdx.x;    // idx = d*1024 + k
    if (idx == 0) g_fix_count = 0;
    int d = idx >> 10, k = idx & 1023;
    float v = C[idx];
    size_t o = (size_t)k * D_DIM + d;
    g_ct[o] = v; g_bhi[o] = __float2bfloat16_rn(v);
}

// ---------------------------------------------------------------------------
// Kernel 1: bf16 mma.sync GEMM (full-rate) + argmin with margin tracking.
// 128 rows, 512 thr, warp grid 4x4, warp tile 32x64, 3-stage pipeline.
// ---------------------------------------------------------------------------
__global__ void __launch_bounds__(512)
k_main(const float* __restrict__ x, const float* __restrict__ cnorm) {
    extern __shared__ char sm[];
    const uint32_t sbase = smem_u32(sm);
    const int tid  = threadIdx.x;
    const int lane = tid & 31, warp = tid >> 5;
    const int wm = warp >> 2, wn = warp & 3;
    const int row0 = blockIdx.x * 128;

    float* scn    = (float*)(sm + SM_CN);
    float* s_pb   = (float*)(sm + SM_PB);
    float* s_ps   = (float*)(sm + SM_PS);
    int*   s_pi   = (int*)  (sm + SM_PI);
    float* s_best = (float*)(sm + SM_BEST);
    float* s_sec  = (float*)(sm + SM_SEC);
    int*   s_bidx = (int*)  (sm + SM_BIDX);

    for (int i = tid; i < K_DIM; i += 512) scn[i] = cnorm[i];
    if (tid < 128) {
        s_best[tid] = __int_as_float(0x7f800000);
        s_sec[tid]  = __int_as_float(0x7f800000);
        s_bidx[tid] = 0;
    }
    __syncthreads();

    // A map: thread -> (row ar = tid>>2, 16 cols at (tid&3)*16)
    const int ar = tid >> 2, aq = tid & 3;
    const float* xrow = x + (size_t)(row0 + ar) * D_DIM + aq * 16;
    const int akey_sts = ar & 7;

    // ldmatrix lane bases (row*128B), XOR-swizzled columns
    const uint32_t a_row = (uint32_t)((wm * 32 + (lane & 15)) * 128);
    const uint32_t b_row = (uint32_t)((wn * 64 + (lane & 7) + ((lane & 16) ? 8 : 0)) * 128);
    const int key = lane & 7;
    const int a_qs = (lane >> 4);
    const int b_qs = (lane >> 3) & 1;

    float acc[2][8][4];
    #pragma unroll
    for (int mt = 0; mt < 2; mt++)
        #pragma unroll
        for (int nt = 0; nt < 8; nt++)
            #pragma unroll
            for (int c = 0; c < 4; c++) acc[mt][nt][c] = 0.f;

    auto bfill = [&](int t, int stage) {
        const __nv_bfloat16* src = g_bhi + (size_t)((t / 12) * 256) * D_DIM + (t % 12) * 64;
        const uint32_t bb = sbase + SM_STG + stage * STG_BYTES + B_OFF;
        #pragma unroll
        for (int i = 0; i < 4; i++) {
            int u = tid + i * 512;
            int n = u >> 3, q = u & 7;
            cpa16(bb + n * 128 + ((q ^ (n & 7)) << 4), src + (size_t)n * D_DIM + q * 8);
        }
        asm volatile("cp.async.commit_group;");
    };
    auto asts = [&](const float4* av, int stage) {
        uint32_t h[8];
        #pragma unroll
        for (int j = 0; j < 4; j++) {
            h[2*j]   = packb2(av[j].x, av[j].y);
            h[2*j+1] = packb2(av[j].z, av[j].w);
        }
        uint32_t da = sbase + SM_STG + stage * STG_BYTES + A_OFF + ar * 128;
        uint32_t o0 = (uint32_t)(((2 * aq)     ^ akey_sts) << 4);
        uint32_t o1 = (uint32_t)(((2 * aq + 1) ^ akey_sts) << 4);
        asm volatile("st.shared.v4.b32 [%0], {%1,%2,%3,%4};"
                     :: "r"(da + o0), "r"(h[0]), "r"(h[1]), "r"(h[2]), "r"(h[3]));
        asm volatile("st.shared.v4.b32 [%0], {%1,%2,%3,%4};"
                     :: "r"(da + o1), "r"(h[4]), "r"(h[5]), "r"(h[6]), "r"(h[7]));
    };

    float4 av[4];
    // ---- prologue ----
    bfill(0, 0);
    {
        const float* p = xrow;
        float4 t0[4] = { *(const float4*)p, *(const float4*)(p+4),
                         *(const float4*)(p+8), *(const float4*)(p+12) };
        asts(t0, 0);
    }
    bfill(1, 1);
    {
        const float* p = xrow + 64;
        av[0] = *(const float4*)p;     av[1] = *(const float4*)(p+4);
        av[2] = *(const float4*)(p+8); av[3] = *(const float4*)(p+12);
    }

    for (int s = 0; s < TOT_IT; s++) {
        const int st = s % N_STAGE;
        if (s + 1 < TOT_IT) asts(av, (s + 1) % N_STAGE);
        if (s + 2 < TOT_IT) {
            const float* p = xrow + ((s + 2) % 12) * 64;
            av[0] = *(const float4*)p;     av[1] = *(const float4*)(p+4);
            av[2] = *(const float4*)(p+8); av[3] = *(const float4*)(p+12);
        }
        asm volatile("cp.async.wait_group 1;");
        __syncthreads();
        if (s + 2 < TOT_IT) bfill(s + 2, (s + 2) % N_STAGE);

        const uint32_t ab = sbase + SM_STG + st * STG_BYTES + A_OFF + a_row;
        const uint32_t bb = sbase + SM_STG + st * STG_BYTES + B_OFF + b_row;
        #pragma unroll
        for (int ks = 0; ks < 4; ks++) {
            uint32_t afr[2][4];
            const uint32_t aoff = (uint32_t)(((ks * 2 + a_qs) ^ key) << 4);
            ldsm4(afr[0], ab + aoff);
            ldsm4(afr[1], ab + 16 * 128 + aoff);
            uint32_t bfr[4][4];
            const uint32_t boff = (uint32_t)(((ks * 2 + b_qs) ^ key) << 4);
            #pragma unroll
            for (int bt = 0; bt < 4; bt++)
                ldsm4(bfr[bt], bb + bt * 16 * 128 + boff);
            #pragma unroll
            for (int mt = 0; mt < 2; mt++)
                #pragma unroll
                for (int nt = 0; nt < 8; nt++)
                    mma16816(acc[mt][nt], afr[mt],
                             bfr[nt >> 1][(nt & 1) * 2],
                             bfr[nt >> 1][(nt & 1) * 2 + 1]);
        }

        if ((s % 12) == 11) {
            const int col0 = (s / 12) * 256;
            #pragma unroll
            for (int mt = 0; mt < 2; mt++) {
                #pragma unroll
                for (int h = 0; h < 2; h++) {
                    float bv = __int_as_float(0x7f800000);
                    float sv = __int_as_float(0x7f800000);
                    int bi = 0;
                    #pragma unroll
                    for (int nt = 0; nt < 8; nt++) {
                        int k0 = col0 + wn * 64 + nt * 8 + (lane & 3) * 2;
                        float v0 = scn[k0]     - 2.0f * acc[mt][nt][h * 2];
                        float v1 = scn[k0 + 1] - 2.0f * acc[mt][nt][h * 2 + 1];
                        if (v0 < bv)      { sv = bv; bv = v0; bi = k0; }
                        else if (v0 < sv) { sv = v0; }
                        if (v1 < bv)      { sv = bv; bv = v1; bi = k0 + 1; }
                        else if (v1 < sv) { sv = v1; }
                    }
                    #pragma unroll
                    for (int m = 1; m <= 2; m <<= 1) {
                        float b2 = __shfl_xor_sync(0xffffffffu, bv, m);
                        float s2 = __shfl_xor_sync(0xffffffffu, sv, m);
                        int   i2 = __shfl_xor_sync(0xffffffffu, bi, m);
                        if (b2 < bv || (b2 == bv && i2 < bi)) {
                            sv = fminf(bv, fminf(sv, s2)); bv = b2; bi = i2;
                        } else {
                            sv = fminf(fminf(sv, s2), b2);
                        }
                    }
                    if ((lane & 3) == 0) {
                        int row = wm * 32 + mt * 16 + h * 8 + (lane >> 2);
                        s_pb[wn * 128 + row] = bv;
                        s_ps[wn * 128 + row] = sv;
                        s_pi[wn * 128 + row] = bi;
                    }
                }
            }
            __syncthreads();
            if (tid < 128) {
                float B = s_pb[tid], S = s_ps[tid]; int I = s_pi[tid];
                #pragma unroll
                for (int w = 1; w < 4; w++) {
                    float b2 = s_pb[w * 128 + tid], s2 = s_ps[w * 128 + tid];
                    int i2 = s_pi[w * 128 + tid];
                    if (b2 < B) { S = fminf(B, fminf(S, s2)); B = b2; I = i2; }
                    else        { S = fminf(fminf(S, s2), b2); }
                }
                float rB = s_best[tid], rS = s_sec[tid]; int rI = s_bidx[tid];
                if (B < rB) { rS = fminf(rB, fminf(rS, S)); rB = B; rI = I; }
                else        { rS = fminf(fminf(rS, S), B); }
                s_best[tid] = rB; s_sec[tid] = rS; s_bidx[tid] = rI;
            }
            __syncthreads();
            #pragma unroll
            for (int mt = 0; mt < 2; mt++)
                #pragma unroll
                for (int nt = 0; nt < 8; nt++)
                    #pragma unroll
                    for (int c = 0; c < 4; c++) acc[mt][nt][c] = 0.f;
        }
    }

    if (tid < 128) {
        int n = row0 + tid;
        g_idx[n] = s_bidx[tid];
        if (s_sec[tid] - s_best[tid] < FIX_THRESH) {
            int slot = atomicAdd(&g_fix_count, 1);
            if (slot < FIX_CAP) g_fix_rows[slot] = n;
        }
    }
}

// ---------------------------------------------------------------------------
// Kernel 2: batched exact fp32 recheck. 12 flagged rows per C sweep:
// x-tile in smem, each thread owns 4 consecutive k-columns, C read from
// row-contiguous g_ct (amortized over 12 rows -> ~12x less L2 than per-row).
// ---------------------------------------------------------------------------
#define FB_ROWS 12
__global__ void __launch_bounds__(256)
k_fixup2(const float* __restrict__ x, const float* __restrict__ cnorm) {
    __shared__ float s_x[FB_ROWS][D_DIM];    // 36.9 KB
    __shared__ float s_rv[256];
    __shared__ int   s_rk[256];
    const int tid = threadIdx.x;
    int cnt = g_fix_count; if (cnt > FIX_CAP) cnt = FIX_CAP;

    for (int base = blockIdx.x * FB_ROWS; base < cnt; base += gridDim.x * FB_ROWS) {
        const int nrows = min(FB_ROWS, cnt - base);
        for (int i = tid; i < nrows * (D_DIM / 4); i += 256) {
            int r = i / (D_DIM / 4), q = i % (D_DIM / 4);
            ((float4*)s_x[r])[q] =
                ((const float4*)(x + (size_t)g_fix_rows[base + r] * D_DIM))[q];
        }
        __syncthreads();

        float best[FB_ROWS]; int bidx[FB_ROWS];
        #pragma unroll
        for (int r = 0; r < FB_ROWS; r++) { best[r] = __int_as_float(0x7f800000); bidx[r] = 0; }

        #pragma unroll 1
        for (int c = 0; c < 4; c++) {
            const int k = tid * 4 + c;
            const float4* cp = (const float4*)(g_ct + (size_t)k * D_DIM);
            const float cn = cnorm[k];
            float acc[FB_ROWS];
            #pragma unroll
            for (int r = 0; r < FB_ROWS; r++) acc[r] = 0.f;
            #pragma unroll 4
            for (int d = 0; d < D_DIM / 4; d++) {
                float4 cv = cp[d];
                #pragma unroll
                for (int r = 0; r < FB_ROWS; r++) {
                    const float* xr = &s_x[r][d * 4];
                    float a = acc[r];
                    a = fmaf(xr[0], cv.x, a); a = fmaf(xr[1], cv.y, a);
                    a = fmaf(xr[2], cv.z, a); a = fmaf(xr[3], cv.w, a);
                    acc[r] = a;
                }
            }
            #pragma unroll
            for (int r = 0; r < FB_ROWS; r++) {
                float val = cn - 2.0f * acc[r];
                if (val < best[r]) { best[r] = val; bidx[r] = k; }   // c ascending -> smallest k kept
            }
        }

        for (int r = 0; r < nrows; r++) {
            s_rv[tid] = best[r]; s_rk[tid] = bidx[r];
            __syncthreads();
            for (int off = 128; off > 0; off >>= 1) {
                if (tid < off) {
                    if (s_rv[tid + off] < s_rv[tid] ||
                        (s_rv[tid + off] == s_rv[tid] && s_rk[tid + off] < s_rk[tid])) {
                        s_rv[tid] = s_rv[tid + off]; s_rk[tid] = s_rk[tid + off];
                    }
                }
                __syncthreads();
            }
            if (tid == 0) g_idx[g_fix_rows[base + r]] = s_rk[0];
            __syncthreads();
        }
        __syncthreads();
    }
}

// ---------------------------------------------------------------------------
// Kernel 3: gather — out[n,:] = CT[idx[n],:]; 16 rows per block.
// ---------------------------------------------------------------------------
__global__ void k_gather(float* __restrict__ out) {
    const int r0 = blockIdx.x * 16;
    const int t = threadIdx.x;
    #pragma unroll
    for (int r = 0; r < 16; r++) {
        const int n = r0 + r;
        const int k = g_idx[n];
        const float4* src = (const float4*)(g_ct + (size_t)k * D_DIM);
        float4* dst = (float4*)(out + (size_t)n * D_DIM);
        dst[t] = src[t];
    }
}

extern "C" void kernel_launch(void* const* d_in, const int* in_sizes, int n_in,
                              void* d_out, int out_size) {
    const float* x     = (const float*)d_in[0];
    const float* C     = (const float*)d_in[1];
    const float* Cnorm = (const float*)d_in[2];
    float* out = (float*)d_out;

    static bool attr_set = false;
    if (!attr_set) {
        cudaFuncSetAttribute(k_main, cudaFuncAttributeMaxDynamicSharedMemorySize, SMEM_TOTAL);
        attr_set = true;
    }

    k_prep<<<(K_DIM * D_DIM) / 256, 256>>>(C);
    k_main<<<N_ROWS / 128, 512, SMEM_TOTAL>>>(x, Cnorm);
    k_fixup2<<<512, 256>>>(x, Cnorm);
    k_gather<<<N_ROWS / 16, 192>>>(out);
}

// round 12
// speedup vs baseline: 2.9357x; 1.5770x over previous
#include <cuda_runtime.h>
#include <cuda_bf16.h>
#include <cstdint>

#define N_ROWS 262144
#define D_DIM  768
#define K_DIM  1024

// ---------------- device scratch ----------------
__device__ float         g_ct [K_DIM * D_DIM];   // fp32 C^T (gather + exact fixup)
__device__ __nv_bfloat16 g_bhi[K_DIM * D_DIM];   // bf16 C^T (K-major)
__device__ int           g_idx[N_ROWS];
__device__ int           g_fix_count;
__device__ int           g_fix_rows[32768];

// ---------------- helpers ----------------
__device__ __forceinline__ uint32_t smem_u32(const void* p) {
    uint32_t a;
    asm("{ .reg .u64 t; cvta.to.shared.u64 t, %1; cvt.u32.u64 %0, t; }" : "=r"(a) : "l"(p));
    return a;
}
__device__ __forceinline__ void cpa16(uint32_t dst, const void* src) {
    asm volatile("{ .reg .u64 p; cvta.to.global.u64 p, %1; cp.async.cg.shared.global [%0], [p], 16; }"
                 :: "r"(dst), "l"(src));
}
__device__ __forceinline__ void ldsm4(uint32_t* r, uint32_t a) {
    asm volatile("ldmatrix.sync.aligned.m8n8.x4.shared.b16 {%0,%1,%2,%3}, [%4];"
                 : "=r"(r[0]), "=r"(r[1]), "=r"(r[2]), "=r"(r[3]) : "r"(a));
}
__device__ __forceinline__ void mma16816(float* c, const uint32_t* a, uint32_t b0, uint32_t b1) {
    asm volatile("mma.sync.aligned.m16n8k16.row.col.f32.bf16.bf16.f32 "
                 "{%0,%1,%2,%3},{%4,%5,%6,%7},{%8,%9},{%0,%1,%2,%3};"
                 : "+f"(c[0]), "+f"(c[1]), "+f"(c[2]), "+f"(c[3])
                 : "r"(a[0]), "r"(a[1]), "r"(a[2]), "r"(a[3]), "r"(b0), "r"(b1));
}
__device__ __forceinline__ uint32_t packb2(float a, float b) {
    __nv_bfloat162 t = __floats2bfloat162_rn(a, b);
    return *reinterpret_cast<uint32_t*>(&t);
}

#define FIX_THRESH 0.87f
#define FIX_CAP    32768

// ---------------- smem layout (dynamic) — proven R5/R7 80B-row layout ----------------
#define SM_CN   0        // 1024 f32
#define SM_PB   4096     // 4 x 128 f32 partials
#define SM_PS   6144
#define SM_PI   8192
#define SM_BEST 10240
#define SM_SEC  10752
#define SM_BIDX 11264
#define SM_STG  12288
#define STG_BYTES 30720  // per stage: A 128x80B + B 256x80B
#define A_HI 0
#define B_HI 10240
#define SMEM_TOTAL (12288 + 2 * 30720)   // 73728

// ---------------------------------------------------------------------------
// Kernel 0: C -> fp32 C^T + bf16 C^T; zero fixup counter
// ---------------------------------------------------------------------------
__global__ void k_prep(const float* __restrict__ C) {
    int idx = blockIdx.x * 256 + threadIdx.x;    // idx = d*1024 + k
    if (idx == 0) g_fix_count = 0;
    int d = idx >> 10, k = idx & 1023;
    float v = C[idx];
    size_t o = (size_t)k * D_DIM + d;
    g_ct[o] = v; g_bhi[o] = __float2bfloat16_rn(v);
}

// ---------------------------------------------------------------------------
// Kernel 1: single-product bf16 mma.sync GEMM + argmin with margin tracking.
// Exact R7 skeleton: 128 rows x (4 chunks of 256 cols), 512 threads,
// warp grid 4x4, warp tile 32x64, 80B padded rows, 2-stage, d-chunk 32.
// ---------------------------------------------------------------------------
__global__ void __launch_bounds__(512, 1)
k_main(const float* __restrict__ x, const float* __restrict__ cnorm) {
    extern __shared__ char sm[];
    const uint32_t sbase = smem_u32(sm);
    const int tid  = threadIdx.x;
    const int lane = tid & 31, warp = tid >> 5;
    const int wm = warp >> 2, wn = warp & 3;
    const int row0 = blockIdx.x * 128;

    float* scn    = (float*)(sm + SM_CN);
    float* s_pb   = (float*)(sm + SM_PB);
    float* s_ps   = (float*)(sm + SM_PS);
    int*   s_pi   = (int*)  (sm + SM_PI);
    float* s_best = (float*)(sm + SM_BEST);
    float* s_sec  = (float*)(sm + SM_SEC);
    int*   s_bidx = (int*)  (sm + SM_BIDX);

    for (int i = tid; i < K_DIM; i += 512) scn[i] = cnorm[i];
    if (tid < 128) {
        s_best[tid] = __int_as_float(0x7f800000);
        s_sec[tid]  = __int_as_float(0x7f800000);
        s_bidx[tid] = 0;
    }
    __syncthreads();

    // A fill mapping: thread -> (row ar, 8 floats at col aq*8)
    const int ar = tid >> 2, aq = tid & 3;
    const float* xp = x + (size_t)(row0 + ar) * D_DIM + aq * 8;
    const uint32_t a_sts = (uint32_t)(ar * 80 + aq * 16);

    // ldmatrix lane base offsets (proven in R5)
    const uint32_t a_ld = (uint32_t)((wm * 32 + (lane & 15)) * 80 + (lane >> 4) * 16);
    const uint32_t b_ld = (uint32_t)((wn * 64 + (lane & 7) + ((lane & 16) ? 8 : 0)) * 80
                                     + ((lane >> 3) & 1) * 16);

    for (int cc = 0; cc < 4; cc++) {
        const int col0 = cc * 256;
        float acc[2][8][4];
        #pragma unroll
        for (int mt = 0; mt < 2; mt++)
            #pragma unroll
            for (int nt = 0; nt < 8; nt++)
                #pragma unroll
                for (int c = 0; c < 4; c++) acc[mt][nt][c] = 0.f;

        // ---- prologue: fill stage 0 ----
        {
            #pragma unroll
            for (int i = 0; i < 2; i++) {
                int idx = tid + i * 512;
                int n = idx >> 2, q = idx & 3;
                cpa16(sbase + SM_STG + B_HI + n * 80 + q * 16,
                      g_bhi + (size_t)(col0 + n) * D_DIM + q * 8);
            }
            asm volatile("cp.async.commit_group;");
            float4 v0 = *(const float4*)(xp);
            float4 v1 = *(const float4*)(xp + 4);
            uint32_t h[4] = { packb2(v0.x, v0.y), packb2(v0.z, v0.w),
                              packb2(v1.x, v1.y), packb2(v1.z, v1.w) };
            asm volatile("st.shared.v4.b32 [%0], {%1,%2,%3,%4};"
                         :: "r"(sbase + SM_STG + A_HI + a_sts),
                            "r"(h[0]), "r"(h[1]), "r"(h[2]), "r"(h[3]));
        }

        for (int dc = 0; dc < 24; dc++) {
            const int buf = dc & 1;
            asm volatile("cp.async.wait_group 0;");
            __syncthreads();

            float4 nv0, nv1;
            const bool more = (dc < 23);
            if (more) {
                const int d0n = (dc + 1) * 32;
                #pragma unroll
                for (int i = 0; i < 2; i++) {
                    int idx = tid + i * 512;
                    int n = idx >> 2, q = idx & 3;
                    cpa16(sbase + SM_STG + (buf ^ 1) * STG_BYTES + B_HI + n * 80 + q * 16,
                          g_bhi + (size_t)(col0 + n) * D_DIM + d0n + q * 8);
                }
                asm volatile("cp.async.commit_group;");
                nv0 = *(const float4*)(xp + d0n);
                nv1 = *(const float4*)(xp + d0n + 4);
            }

            // ---- compute: 2 k16-steps x 16 mmas ----
            const uint32_t stg = sbase + SM_STG + buf * STG_BYTES;
            const uint32_t ab = stg + A_HI + a_ld;
            const uint32_t bb = stg + B_HI + b_ld;
            #pragma unroll
            for (int ks = 0; ks < 2; ks++) {
                uint32_t afr[2][4];
                ldsm4(afr[0], ab + ks * 32);
                ldsm4(afr[1], ab + 1280 + ks * 32);          // +16 rows * 80B
                uint32_t bfr[4][4];
                #pragma unroll
                for (int bt = 0; bt < 4; bt++)
                    ldsm4(bfr[bt], bb + bt * 1280 + ks * 32);
                #pragma unroll
                for (int mt = 0; mt < 2; mt++)
                    #pragma unroll
                    for (int nt = 0; nt < 8; nt++)
                        mma16816(acc[mt][nt], afr[mt],
                                 bfr[nt >> 1][(nt & 1) * 2],
                                 bfr[nt >> 1][(nt & 1) * 2 + 1]);
            }

            if (more) {
                uint32_t h[4] = { packb2(nv0.x, nv0.y), packb2(nv0.z, nv0.w),
                                  packb2(nv1.x, nv1.y), packb2(nv1.z, nv1.w) };
                asm volatile("st.shared.v4.b32 [%0], {%1,%2,%3,%4};"
                             :: "r"(sbase + SM_STG + (buf ^ 1) * STG_BYTES + A_HI + a_sts),
                                "r"(h[0]), "r"(h[1]), "r"(h[2]), "r"(h[3]));
            }
        }

        // ---- epilogue for this 256-col chunk (best + second-best + index) ----
        #pragma unroll
        for (int mt = 0; mt < 2; mt++) {
            #pragma unroll
            for (int h = 0; h < 2; h++) {
                float bv = __int_as_float(0x7f800000);
                float sv = __int_as_float(0x7f800000);
                int bi = 0;
                #pragma unroll
                for (int nt = 0; nt < 8; nt++) {
                    int k0 = col0 + wn * 64 + nt * 8 + (lane & 3) * 2;
                    float v0 = scn[k0]     - 2.0f * acc[mt][nt][h * 2];
                    float v1 = scn[k0 + 1] - 2.0f * acc[mt][nt][h * 2 + 1];
                    if (v0 < bv)      { sv = bv; bv = v0; bi = k0; }
                    else if (v0 < sv) { sv = v0; }
                    if (v1 < bv)      { sv = bv; bv = v1; bi = k0 + 1; }
                    else if (v1 < sv) { sv = v1; }
                }
                #pragma unroll
                for (int m = 1; m <= 2; m <<= 1) {
                    float b2 = __shfl_xor_sync(0xffffffffu, bv, m);
                    float s2 = __shfl_xor_sync(0xffffffffu, sv, m);
                    int   i2 = __shfl_xor_sync(0xffffffffu, bi, m);
                    if (b2 < bv || (b2 == bv && i2 < bi)) {
                        sv = fminf(bv, fminf(sv, s2)); bv = b2; bi = i2;
                    } else {
                        sv = fminf(fminf(sv, s2), b2);
                    }
                }
                if ((lane & 3) == 0) {
                    int row = wm * 32 + mt * 16 + h * 8 + (lane >> 2);
                    s_pb[wn * 128 + row] = bv;
                    s_ps[wn * 128 + row] = sv;
                    s_pi[wn * 128 + row] = bi;
                }
            }
        }
        __syncthreads();
        if (tid < 128) {
            float B = s_pb[tid], S = s_ps[tid]; int I = s_pi[tid];
            #pragma unroll
            for (int w = 1; w < 4; w++) {
                float b2 = s_pb[w * 128 + tid], s2 = s_ps[w * 128 + tid];
                int i2 = s_pi[w * 128 + tid];
                if (b2 < B) { S = fminf(B, fminf(S, s2)); B = b2; I = i2; }
                else        { S = fminf(fminf(S, s2), b2); }
            }
            float rB = s_best[tid], rS = s_sec[tid]; int rI = s_bidx[tid];
            if (B < rB) { rS = fminf(rB, fminf(rS, S)); rB = B; rI = I; }
            else        { rS = fminf(fminf(rS, S), B); }
            s_best[tid] = rB; s_sec[tid] = rS; s_bidx[tid] = rI;
        }
        __syncthreads();
    }

    if (tid < 128) {
        int n = row0 + tid;
        g_idx[n] = s_bidx[tid];
        if (s_sec[tid] - s_best[tid] < FIX_THRESH) {
            int slot = atomicAdd(&g_fix_count, 1);
            if (slot < FIX_CAP) g_fix_rows[slot] = n;
        }
    }
}

// ---------------------------------------------------------------------------
// Kernel 2: batched exact fp32 recheck (12 flagged rows per C sweep).
// ---------------------------------------------------------------------------
#define FB_ROWS 12
__global__ void __launch_bounds__(256)
k_fixup2(const float* __restrict__ x, const float* __restrict__ cnorm) {
    __shared__ float s_x[FB_ROWS][D_DIM];    // 36.9 KB
    __shared__ float s_rv[256];
    __shared__ int   s_rk[256];
    const int tid = threadIdx.x;
    int cnt = g_fix_count; if (cnt > FIX_CAP) cnt = FIX_CAP;

    for (int base = blockIdx.x * FB_ROWS; base < cnt; base += gridDim.x * FB_ROWS) {
        const int nrows = min(FB_ROWS, cnt - base);
        for (int i = tid; i < nrows * (D_DIM / 4); i += 256) {
            int r = i / (D_DIM / 4), q = i % (D_DIM / 4);
            ((float4*)s_x[r])[q] =
                ((const float4*)(x + (size_t)g_fix_rows[base + r] * D_DIM))[q];
        }
        __syncthreads();

        float best[FB_ROWS]; int bidx[FB_ROWS];
        #pragma unroll
        for (int r = 0; r < FB_ROWS; r++) { best[r] = __int_as_float(0x7f800000); bidx[r] = 0; }

        #pragma unroll 1
        for (int c = 0; c < 4; c++) {
            const int k = tid * 4 + c;
            const float4* cp = (const float4*)(g_ct + (size_t)k * D_DIM);
            const float cn = cnorm[k];
            float acc[FB_ROWS];
            #pragma unroll
            for (int r = 0; r < FB_ROWS; r++) acc[r] = 0.f;
            #pragma unroll 4
            for (int d = 0; d < D_DIM / 4; d++) {
                float4 cv = cp[d];
                #pragma unroll
                for (int r = 0; r < FB_ROWS; r++) {
                    const float* xr = &s_x[r][d * 4];
                    float a = acc[r];
                    a = fmaf(xr[0], cv.x, a); a = fmaf(xr[1], cv.y, a);
                    a = fmaf(xr[2], cv.z, a); a = fmaf(xr[3], cv.w, a);
                    acc[r] = a;
                }
            }
            #pragma unroll
            for (int r = 0; r < FB_ROWS; r++) {
                float val = cn - 2.0f * acc[r];
                if (val < best[r]) { best[r] = val; bidx[r] = k; }
            }
        }

        for (int r = 0; r < nrows; r++) {
            s_rv[tid] = best[r]; s_rk[tid] = bidx[r];
            __syncthreads();
            for (int off = 128; off > 0; off >>= 1) {
                if (tid < off) {
                    if (s_rv[tid + off] < s_rv[tid] ||
                        (s_rv[tid + off] == s_rv[tid] && s_rk[tid + off] < s_rk[tid])) {
                        s_rv[tid] = s_rv[tid + off]; s_rk[tid] = s_rk[tid + off];
                    }
                }
                __syncthreads();
            }
            if (tid == 0) g_idx[g_fix_rows[base + r]] = s_rk[0];
            __syncthreads();
        }
        __syncthreads();
    }
}

// ---------------------------------------------------------------------------
// Kernel 3: gather — out[n,:] = CT[idx[n],:]; 16 rows per block.
// ---------------------------------------------------------------------------
__global__ void k_gather(float* __restrict__ out) {
    const int r0 = blockIdx.x * 16;
    const int t = threadIdx.x;
    #pragma unroll
    for (int r = 0; r < 16; r++) {
        const int n = r0 + r;
        const int k = g_idx[n];
        const float4* src = (const float4*)(g_ct + (size_t)k * D_DIM);
        float4* dst = (float4*)(out + (size_t)n * D_DIM);
        dst[t] = src[t];
    }
}

extern "C" void kernel_launch(void* const* d_in, const int* in_sizes, int n_in,
                              void* d_out, int out_size) {
    const float* x     = (const float*)d_in[0];
    const float* C     = (const float*)d_in[1];
    const float* Cnorm = (const float*)d_in[2];
    float* out = (float*)d_out;

    static bool attr_set = false;
    if (!attr_set) {
        cudaFuncSetAttribute(k_main, cudaFuncAttributeMaxDynamicSharedMemorySize, SMEM_TOTAL);
        attr_set = true;
    }

    k_prep<<<(K_DIM * D_DIM) / 256, 256>>>(C);
    k_main<<<N_ROWS / 128, 512, SMEM_TOTAL>>>(x, Cnorm);
    k_fixup2<<<512, 256>>>(x, Cnorm);
    k_gather<<<N_ROWS / 16, 192>>>(out);
}